// round 1
// baseline (speedup 1.0000x reference)
#include <cuda_runtime.h>
#include <math.h>
#include <stdint.h>

// ---------------- problem constants ----------------
#define NB 2            // batch
#define CH 256          // channels
#define SV 32768L       // spatial voxels 32*32*32
#define NH 4            // heads
#define HD 64           // head dim
#define SCALE_INV 0.0625f  // 1/sqrt(256)
#define EPS 1e-6f

// ---------------- scratch (static device globals; allocation-free) -------
__device__ float g_qkv   [NB * 768L * SV];     // qkv conv output
__device__ float g_attn  [NB * 256L * SV];     // x + local attn, then normalized in place
__device__ float g_q2    [NB * 256L * SV];     // q conv output
__device__ float g_g     [NB * 256L * SV];     // global attn + residual
__device__ float g_pooled[NB * 256 * 512];
__device__ float g_kv2   [NB * 512 * 512];
__device__ float g_part  [NB * 512 * 2];       // reduction partials
__device__ float g_stats [NB * 2];             // sum, sumsq
__device__ float g_aff   [6 * NB * 256];       // A0 D0 A1 D1 A2 D2

// =========================================================================
// Deterministic two-stage mean/var reduction
// =========================================================================
__global__ void reduce1_kernel(const float* __restrict__ buf, long per, float* __restrict__ part) {
    int n = blockIdx.y;
    const float* p = buf + (size_t)n * per;
    float s = 0.f, ss = 0.f;
    for (long i = (long)blockIdx.x * blockDim.x + threadIdx.x; i < per;
         i += (long)gridDim.x * blockDim.x) {
        float v = p[i];
        s += v; ss += v * v;
    }
    // warp reduce
    for (int o = 16; o; o >>= 1) {
        s  += __shfl_down_sync(0xffffffffu, s, o);
        ss += __shfl_down_sync(0xffffffffu, ss, o);
    }
    __shared__ float sh[64];
    int w = threadIdx.x >> 5;
    if ((threadIdx.x & 31) == 0) { sh[w] = s; sh[32 + w] = ss; }
    __syncthreads();
    if (threadIdx.x < 32) {
        int nw = blockDim.x >> 5;
        s  = (threadIdx.x < nw) ? sh[threadIdx.x]      : 0.f;
        ss = (threadIdx.x < nw) ? sh[32 + threadIdx.x] : 0.f;
        for (int o = 16; o; o >>= 1) {
            s  += __shfl_down_sync(0xffffffffu, s, o);
            ss += __shfl_down_sync(0xffffffffu, ss, o);
        }
        if (threadIdx.x == 0) {
            part[((size_t)n * gridDim.x + blockIdx.x) * 2 + 0] = s;
            part[((size_t)n * gridDim.x + blockIdx.x) * 2 + 1] = ss;
        }
    }
}

__global__ void reduce2_kernel(const float* __restrict__ part, int nb, float* __restrict__ stats) {
    int n = blockIdx.x;
    float s = 0.f, ss = 0.f;
    for (int i = threadIdx.x; i < nb; i += blockDim.x) {
        s  += part[((size_t)n * nb + i) * 2 + 0];
        ss += part[((size_t)n * nb + i) * 2 + 1];
    }
    for (int o = 16; o; o >>= 1) {
        s  += __shfl_down_sync(0xffffffffu, s, o);
        ss += __shfl_down_sync(0xffffffffu, ss, o);
    }
    __shared__ float sh[64];
    int w = threadIdx.x >> 5;
    if ((threadIdx.x & 31) == 0) { sh[w] = s; sh[32 + w] = ss; }
    __syncthreads();
    if (threadIdx.x < 32) {
        int nw = blockDim.x >> 5;
        s  = (threadIdx.x < nw) ? sh[threadIdx.x]      : 0.f;
        ss = (threadIdx.x < nw) ? sh[32 + threadIdx.x] : 0.f;
        for (int o = 16; o; o >>= 1) {
            s  += __shfl_down_sync(0xffffffffu, s, o);
            ss += __shfl_down_sync(0xffffffffu, ss, o);
        }
        if (threadIdx.x == 0) { stats[n * 2] = s; stats[n * 2 + 1] = ss; }
    }
}

// per-(n,c) affine for groupnorm folded into GEMM A-load: xn = a*x + d
__global__ void make_affine_kernel(const float* __restrict__ stats,
                                   const float* __restrict__ w, const float* __restrict__ b,
                                   float* __restrict__ a, float* __restrict__ d, float inv_cnt) {
    int c = threadIdx.x;
    int n = blockIdx.x;
    float mean = stats[n * 2] * inv_cnt;
    float var  = stats[n * 2 + 1] * inv_cnt - mean * mean;
    float rstd = rsqrtf(var + EPS);
    a[n * CH + c] = w[c] * rstd;
    d[n * CH + c] = b[c] - mean * rstd * w[c];
}

// elementwise in-place normalize: buf = a[n,c]*buf + d[n,c]   (float4)
__global__ void apply_norm_kernel(float* __restrict__ buf,
                                  const float* __restrict__ a, const float* __restrict__ d) {
    size_t i4 = (size_t)blockIdx.x * blockDim.x + threadIdx.x;  // over float4s
    int c = (int)((i4 >> 13) & 255);    // 8192 float4 per channel
    int n = (int)(i4 >> 21);            // 2097152 float4 per sample
    float aa = a[n * CH + c], dd = d[n * CH + c];
    float4 v = reinterpret_cast<float4*>(buf)[i4];
    v.x = aa * v.x + dd; v.y = aa * v.y + dd; v.z = aa * v.z + dd; v.w = aa * v.w + dd;
    reinterpret_cast<float4*>(buf)[i4] = v;
}

// 4x4x4 average pool: [N,C,32,32,32] -> [N,C,8,8,8]
__global__ void pool_kernel(const float* __restrict__ attn, float* __restrict__ pooled) {
    int idx = blockIdx.x * blockDim.x + threadIdx.x;   // NB*256*512
    if (idx >= NB * 256 * 512) return;
    int p = idx & 511, c = (idx >> 9) & 255, n = idx >> 17;
    int ph = p >> 6, pw = (p >> 3) & 7, pd = p & 7;
    const float* base = attn + ((size_t)n * CH + c) * SV;
    float s = 0.f;
    #pragma unroll
    for (int i = 0; i < 4; i++)
        #pragma unroll
        for (int j = 0; j < 4; j++)
            #pragma unroll
            for (int k = 0; k < 4; k++)
                s += base[((ph * 4 + i) * 32 + (pw * 4 + j)) * 32 + (pd * 4 + k)];
    pooled[((size_t)n * CH + c) * 512 + p] = s * (1.f / 64.f);
}

// =========================================================================
// SGEMM: out[n,m,s] = sum_c W[m,c] * (a[n,c]*X[n,c,s]+d[n,c]) + bias[m]
// K fixed = 256. Tiles: 64(M) x 64(S) x 16(K). 256 threads, 4x4 microtile.
// =========================================================================
__global__ void __launch_bounds__(256) gemm_kernel(
    const float* __restrict__ W, const float* __restrict__ X,
    const float* __restrict__ bias,
    const float* __restrict__ affA, const float* __restrict__ affD,
    float* __restrict__ out, int M, int S) {
    __shared__ float Ws[16][64];
    __shared__ float Xs[16][64];

    int tid = threadIdx.x;
    int tx = tid & 15, ty = tid >> 4;
    int s0 = blockIdx.x * 64;
    int m0 = blockIdx.y * 64;
    int z  = blockIdx.z;

    const float* Xb = X + (size_t)z * 256 * S;
    float* Ob = out + (size_t)z * M * S;
    const float* aA = affA ? affA + z * CH : nullptr;
    const float* aD = affD ? affD + z * CH : nullptr;

    float acc[4][4];
    #pragma unroll
    for (int i = 0; i < 4; i++)
        #pragma unroll
        for (int j = 0; j < 4; j++) acc[i][j] = 0.f;

    int omL = tid >> 2, kgL = tid & 3;     // W-tile load coords
    int kcL = tid >> 4, ogL = tid & 15;    // X-tile load coords

    for (int kt = 0; kt < 16; kt++) {
        int k0 = kt * 16;
        float4 w4 = *reinterpret_cast<const float4*>(&W[(size_t)(m0 + omL) * 256 + k0 + kgL * 4]);
        float4 xv = *reinterpret_cast<const float4*>(&Xb[(size_t)(k0 + kcL) * S + s0 + ogL * 4]);
        if (aA) {
            float a = aA[k0 + kcL], d = aD[k0 + kcL];
            xv.x = a * xv.x + d; xv.y = a * xv.y + d; xv.z = a * xv.z + d; xv.w = a * xv.w + d;
        }
        Ws[kgL * 4 + 0][omL] = w4.x;
        Ws[kgL * 4 + 1][omL] = w4.y;
        Ws[kgL * 4 + 2][omL] = w4.z;
        Ws[kgL * 4 + 3][omL] = w4.w;
        *reinterpret_cast<float4*>(&Xs[kcL][ogL * 4]) = xv;
        __syncthreads();

        #pragma unroll
        for (int kc = 0; kc < 16; kc++) {
            float4 a4 = *reinterpret_cast<const float4*>(&Ws[kc][ty * 4]);
            float4 b4 = *reinterpret_cast<const float4*>(&Xs[kc][tx * 4]);
            float av[4] = {a4.x, a4.y, a4.z, a4.w};
            float bv[4] = {b4.x, b4.y, b4.z, b4.w};
            #pragma unroll
            for (int i = 0; i < 4; i++)
                #pragma unroll
                for (int j = 0; j < 4; j++) acc[i][j] += av[i] * bv[j];
        }
        __syncthreads();
    }

    #pragma unroll
    for (int i = 0; i < 4; i++) {
        int m = m0 + ty * 4 + i;
        float bv = bias[m];
        float4 r;
        r.x = acc[i][0] + bv; r.y = acc[i][1] + bv; r.z = acc[i][2] + bv; r.w = acc[i][3] + bv;
        *reinterpret_cast<float4*>(&Ob[(size_t)m * S + s0 + tx * 4]) = r;
    }
}

// =========================================================================
// Local windowed attention: one block per (window, head, n); 64 threads,
// one query row each. out = x + attn   (GroupNorm applied later in place)
// =========================================================================
__global__ void __launch_bounds__(64) local_attn_kernel(
    const float* __restrict__ qkv, const float* __restrict__ x, float* __restrict__ out) {
    __shared__ float Ks[64][64];
    __shared__ float Vs[64][64];
    int w = blockIdx.x, head = blockIdx.y, n = blockIdx.z;
    int tid = threadIdx.x;
    const float* qkvn = qkv + (size_t)n * 768 * SV;
    int wh = w >> 6, ww = (w >> 3) & 7, wd = w & 7;
    int base_s = ((wh * 4) * 32 + ww * 4) * 32 + wd * 4;

    // stage K, V tiles (64 tokens x 64 dims)
    for (int idx = tid; idx < 4096; idx += 64) {
        int t = idx & 63, hd = idx >> 6;
        int s = base_s + (t >> 4) * 1024 + ((t >> 2) & 3) * 32 + (t & 3);
        Ks[t][hd] = qkvn[(size_t)(256 + head * 64 + hd) * SV + s];
        Vs[t][hd] = qkvn[(size_t)(512 + head * 64 + hd) * SV + s];
    }
    int sr = base_s + (tid >> 4) * 1024 + ((tid >> 2) & 3) * 32 + (tid & 3);
    float q[64];
    #pragma unroll
    for (int hd = 0; hd < 64; hd++)
        q[hd] = qkvn[(size_t)(head * 64 + hd) * SV + sr] * SCALE_INV;
    __syncthreads();

    // scores
    float sc[64];
    float m = -1e30f;
    for (int c = 0; c < 64; c++) {
        const float4* k4 = reinterpret_cast<const float4*>(Ks[c]);
        float s_ = 0.f;
        #pragma unroll
        for (int h = 0; h < 16; h++) {
            float4 kk = k4[h];
            s_ += q[4*h+0]*kk.x + q[4*h+1]*kk.y + q[4*h+2]*kk.z + q[4*h+3]*kk.w;
        }
        sc[c] = s_;
        m = fmaxf(m, s_);
    }
    float l = 0.f;
    #pragma unroll
    for (int c = 0; c < 64; c++) { sc[c] = __expf(sc[c] - m); l += sc[c]; }
    float inv = 1.f / l;

    // O = P @ V
    float o[64];
    #pragma unroll
    for (int h = 0; h < 64; h++) o[h] = 0.f;
    for (int t = 0; t < 64; t++) {
        float p = sc[t];
        const float4* v4 = reinterpret_cast<const float4*>(Vs[t]);
        #pragma unroll
        for (int h = 0; h < 16; h++) {
            float4 vv = v4[h];
            o[4*h+0] += p*vv.x; o[4*h+1] += p*vv.y; o[4*h+2] += p*vv.z; o[4*h+3] += p*vv.w;
        }
    }
    const float* xn = x   + ((size_t)n * CH + head * 64) * SV;
    float* on       = out + ((size_t)n * CH + head * 64) * SV;
    #pragma unroll
    for (int hd = 0; hd < 64; hd++)
        on[(size_t)hd * SV + sr] = xn[(size_t)hd * SV + sr] + o[hd] * inv;
}

// =========================================================================
// Global attention: 32768 queries per (n,head) vs 512 keys; one thread per
// query, online softmax, K/V chunks in smem. g = attn_out + attn_x.
// =========================================================================
__global__ void __launch_bounds__(128) global_attn_kernel(
    const float* __restrict__ q2, const float* __restrict__ kv2,
    const float* __restrict__ attn, float* __restrict__ g) {
    __shared__ float Ks[64][64];
    __shared__ float Vs[64][64];
    int n = blockIdx.z, head = blockIdx.y;
    int s = blockIdx.x * 128 + threadIdx.x;
    const float* qn = q2  + ((size_t)n * 256 + head * 64) * SV;
    const float* kn = kv2 + ((size_t)n * 512 + head * 64) * 512;
    const float* vn = kn + 256 * 512;

    float q[64];
    #pragma unroll
    for (int hd = 0; hd < 64; hd++) q[hd] = qn[(size_t)hd * SV + s] * SCALE_INV;

    float o[64];
    #pragma unroll
    for (int hd = 0; hd < 64; hd++) o[hd] = 0.f;
    float m = -1e30f, l = 0.f;

    for (int c0 = 0; c0 < 512; c0 += 64) {
        __syncthreads();
        for (int idx = threadIdx.x; idx < 4096; idx += 128) {
            int j = idx & 63, hd = idx >> 6;
            Ks[j][hd] = kn[hd * 512 + c0 + j];
            Vs[j][hd] = vn[hd * 512 + c0 + j];
        }
        __syncthreads();
        for (int j = 0; j < 64; j++) {
            const float4* k4 = reinterpret_cast<const float4*>(Ks[j]);
            float sc = 0.f;
            #pragma unroll
            for (int h = 0; h < 16; h++) {
                float4 kk = k4[h];
                sc += q[4*h+0]*kk.x + q[4*h+1]*kk.y + q[4*h+2]*kk.z + q[4*h+3]*kk.w;
            }
            if (sc > m) {
                float corr = __expf(m - sc);
                l *= corr;
                #pragma unroll
                for (int hd = 0; hd < 64; hd++) o[hd] *= corr;
                m = sc;
            }
            float p = __expf(sc - m);
            l += p;
            const float4* v4 = reinterpret_cast<const float4*>(Vs[j]);
            #pragma unroll
            for (int h = 0; h < 16; h++) {
                float4 vv = v4[h];
                o[4*h+0] += p*vv.x; o[4*h+1] += p*vv.y; o[4*h+2] += p*vv.z; o[4*h+3] += p*vv.w;
            }
        }
    }
    float inv = 1.f / l;
    const float* an = attn + ((size_t)n * 256 + head * 64) * SV;
    float* gn       = g    + ((size_t)n * 256 + head * 64) * SV;
    #pragma unroll
    for (int hd = 0; hd < 64; hd++)
        gn[(size_t)hd * SV + s] = o[hd] * inv + an[(size_t)hd * SV + s];
}

// =========================================================================
// host launch
// =========================================================================
static float* sym(const void* p) { return (float*)p; }

extern "C" void kernel_launch(void* const* d_in, const int* in_sizes, int n_in,
                              void* d_out, int out_size) {
    const float* x      = (const float*)d_in[0];
    const float* qkv_w  = (const float*)d_in[1];
    const float* qkv_b  = (const float*)d_in[2];
    const float* norm_w = (const float*)d_in[3];
    const float* norm_b = (const float*)d_in[4];
    const float* anorm_w= (const float*)d_in[5];
    const float* anorm_b= (const float*)d_in[6];
    const float* dnorm_w= (const float*)d_in[7];
    const float* dnorm_b= (const float*)d_in[8];
    const float* q_w    = (const float*)d_in[9];
    const float* q_b    = (const float*)d_in[10];
    const float* kv_w   = (const float*)d_in[11];
    const float* kv_b   = (const float*)d_in[12];
    const float* proj_w = (const float*)d_in[13];
    const float* proj_b = (const float*)d_in[14];
    float* out = (float*)d_out;

    float *qkv, *attn, *q2, *gg, *pooled, *kv2, *part, *stats, *aff;
    cudaGetSymbolAddress((void**)&qkv,    g_qkv);
    cudaGetSymbolAddress((void**)&attn,   g_attn);
    cudaGetSymbolAddress((void**)&q2,     g_q2);
    cudaGetSymbolAddress((void**)&gg,     g_g);
    cudaGetSymbolAddress((void**)&pooled, g_pooled);
    cudaGetSymbolAddress((void**)&kv2,    g_kv2);
    cudaGetSymbolAddress((void**)&part,   g_part);
    cudaGetSymbolAddress((void**)&stats,  g_stats);
    cudaGetSymbolAddress((void**)&aff,    g_aff);

    float* A0 = aff;            float* D0 = aff + 512;
    float* A1 = aff + 1024;     float* D1 = aff + 1536;
    float* A2 = aff + 2048;     float* D2 = aff + 2560;

    // --- GroupNorm(x) stats -> affine, folded into qkv GEMM ---
    reduce1_kernel<<<dim3(512, NB), 256>>>(x, 256L * SV, part);
    reduce2_kernel<<<NB, 256>>>(part, 512, stats);
    make_affine_kernel<<<NB, 256>>>(stats, norm_w, norm_b, A0, D0, 1.f / (256.f * 32768.f));

    // --- qkv = W_qkv @ norm(x) + b ---
    gemm_kernel<<<dim3(512, 12, NB), 256>>>(qkv_w, x, qkv_b, A0, D0, qkv, 768, (int)SV);

    // --- local windowed attention, attn = x + attn_out ---
    local_attn_kernel<<<dim3(512, NH, NB), 64>>>(qkv, x, attn);

    // --- GroupNorm(x + attn) in place ---
    reduce1_kernel<<<dim3(512, NB), 256>>>(attn, 256L * SV, part);
    reduce2_kernel<<<NB, 256>>>(part, 512, stats);
    make_affine_kernel<<<NB, 256>>>(stats, anorm_w, anorm_b, A1, D1, 1.f / (256.f * 32768.f));
    apply_norm_kernel<<<16384, 256>>>(attn, A1, D1);

    // --- 4x pool + GroupNorm affine + kv conv ---
    pool_kernel<<<1024, 256>>>(attn, pooled);
    reduce1_kernel<<<dim3(32, NB), 256>>>(pooled, 256L * 512, part);
    reduce2_kernel<<<NB, 256>>>(part, 32, stats);
    make_affine_kernel<<<NB, 256>>>(stats, dnorm_w, dnorm_b, A2, D2, 1.f / (256.f * 512.f));
    gemm_kernel<<<dim3(8, 8, NB), 256>>>(kv_w, pooled, kv_b, A2, D2, kv2, 512, 512);

    // --- q conv on attn_x ---
    gemm_kernel<<<dim3(512, 4, NB), 256>>>(q_w, attn, q_b, nullptr, nullptr, q2, 256, (int)SV);

    // --- global attention + residual ---
    global_attn_kernel<<<dim3(256, NH, NB), 128>>>(q2, kv2, attn, gg);

    // --- final projection -> out ---
    gemm_kernel<<<dim3(512, 4, NB), 256>>>(proj_w, gg, proj_b, nullptr, nullptr, out, 256, (int)SV);
}

// round 2
// speedup vs baseline: 1.7566x; 1.7566x over previous
#include <cuda_runtime.h>
#include <cuda_bf16.h>
#include <mma.h>
#include <math.h>
#include <stdint.h>

using namespace nvcuda;

// ---------------- problem constants ----------------
#define NB 2
#define CH 256
#define SV 32768L
#define NH 4
#define HD 64
#define SCALE_INV 0.0625f
#define EPS 1e-6f

// ---------------- scratch ----------------
__device__ __align__(16) float g_qkv   [NB * 768L * SV];
__device__ __align__(16) float g_attn  [NB * 256L * SV];
__device__ __align__(16) float g_g     [NB * 256L * SV];
__device__ __align__(16) float g_pooled[NB * 256 * 512];
__device__ __align__(16) __nv_bfloat16 g_q2T[NB * 4L * SV * 64];
__device__ __align__(16) __nv_bfloat16 g_kvT[NB * 8L * 512 * 64];
__device__ float g_part [NB * 512 * 2];
__device__ float g_stats[NB * 2];
__device__ float g_aff  [6 * NB * 256];

// =========================================================================
// reductions / affine / elementwise (unchanged from round 1)
// =========================================================================
__global__ void reduce1_kernel(const float* __restrict__ buf, long per, float* __restrict__ part) {
    int n = blockIdx.y;
    const float* p = buf + (size_t)n * per;
    float s = 0.f, ss = 0.f;
    for (long i = (long)blockIdx.x * blockDim.x + threadIdx.x; i < per;
         i += (long)gridDim.x * blockDim.x) {
        float v = p[i];
        s += v; ss += v * v;
    }
    for (int o = 16; o; o >>= 1) {
        s  += __shfl_down_sync(0xffffffffu, s, o);
        ss += __shfl_down_sync(0xffffffffu, ss, o);
    }
    __shared__ float sh[64];
    int w = threadIdx.x >> 5;
    if ((threadIdx.x & 31) == 0) { sh[w] = s; sh[32 + w] = ss; }
    __syncthreads();
    if (threadIdx.x < 32) {
        int nw = blockDim.x >> 5;
        s  = (threadIdx.x < nw) ? sh[threadIdx.x]      : 0.f;
        ss = (threadIdx.x < nw) ? sh[32 + threadIdx.x] : 0.f;
        for (int o = 16; o; o >>= 1) {
            s  += __shfl_down_sync(0xffffffffu, s, o);
            ss += __shfl_down_sync(0xffffffffu, ss, o);
        }
        if (threadIdx.x == 0) {
            part[((size_t)n * gridDim.x + blockIdx.x) * 2 + 0] = s;
            part[((size_t)n * gridDim.x + blockIdx.x) * 2 + 1] = ss;
        }
    }
}

__global__ void reduce2_kernel(const float* __restrict__ part, int nb, float* __restrict__ stats) {
    int n = blockIdx.x;
    float s = 0.f, ss = 0.f;
    for (int i = threadIdx.x; i < nb; i += blockDim.x) {
        s  += part[((size_t)n * nb + i) * 2 + 0];
        ss += part[((size_t)n * nb + i) * 2 + 1];
    }
    for (int o = 16; o; o >>= 1) {
        s  += __shfl_down_sync(0xffffffffu, s, o);
        ss += __shfl_down_sync(0xffffffffu, ss, o);
    }
    __shared__ float sh[64];
    int w = threadIdx.x >> 5;
    if ((threadIdx.x & 31) == 0) { sh[w] = s; sh[32 + w] = ss; }
    __syncthreads();
    if (threadIdx.x < 32) {
        int nw = blockDim.x >> 5;
        s  = (threadIdx.x < nw) ? sh[threadIdx.x]      : 0.f;
        ss = (threadIdx.x < nw) ? sh[32 + threadIdx.x] : 0.f;
        for (int o = 16; o; o >>= 1) {
            s  += __shfl_down_sync(0xffffffffu, s, o);
            ss += __shfl_down_sync(0xffffffffu, ss, o);
        }
        if (threadIdx.x == 0) { stats[n * 2] = s; stats[n * 2 + 1] = ss; }
    }
}

__global__ void make_affine_kernel(const float* __restrict__ stats,
                                   const float* __restrict__ w, const float* __restrict__ b,
                                   float* __restrict__ a, float* __restrict__ d, float inv_cnt) {
    int c = threadIdx.x;
    int n = blockIdx.x;
    float mean = stats[n * 2] * inv_cnt;
    float var  = stats[n * 2 + 1] * inv_cnt - mean * mean;
    float rstd = rsqrtf(var + EPS);
    a[n * CH + c] = w[c] * rstd;
    d[n * CH + c] = b[c] - mean * rstd * w[c];
}

__global__ void apply_norm_kernel(float* __restrict__ buf,
                                  const float* __restrict__ a, const float* __restrict__ d) {
    size_t i4 = (size_t)blockIdx.x * blockDim.x + threadIdx.x;
    int c = (int)((i4 >> 13) & 255);
    int n = (int)(i4 >> 21);
    float aa = a[n * CH + c], dd = d[n * CH + c];
    float4 v = reinterpret_cast<float4*>(buf)[i4];
    v.x = aa * v.x + dd; v.y = aa * v.y + dd; v.z = aa * v.z + dd; v.w = aa * v.w + dd;
    reinterpret_cast<float4*>(buf)[i4] = v;
}

__global__ void pool_kernel(const float* __restrict__ attn, float* __restrict__ pooled) {
    int idx = blockIdx.x * blockDim.x + threadIdx.x;
    if (idx >= NB * 256 * 512) return;
    int p = idx & 511, c = (idx >> 9) & 255, n = idx >> 17;
    int ph = p >> 6, pw = (p >> 3) & 7, pd = p & 7;
    const float* base = attn + ((size_t)n * CH + c) * SV;
    float s = 0.f;
    #pragma unroll
    for (int i = 0; i < 4; i++)
        #pragma unroll
        for (int j = 0; j < 4; j++)
            #pragma unroll
            for (int k = 0; k < 4; k++)
                s += base[((ph * 4 + i) * 32 + (pw * 4 + j)) * 32 + (pd * 4 + k)];
    pooled[((size_t)n * CH + c) * 512 + p] = s * (1.f / 64.f);
}

// =========================================================================
// wmma bf16 GEMM: out[z,m,s] = sum_k W[m,k] * fold(X[z,k,s]) + bias[m]
// split=1: logical K=768 = [hiW|loW|hiW] x [hiX|hiX|loX]  (3xBF16, physical K=256)
// outF: fp32 [z][M][S].   outB: bf16 [(z*(M/64)+m0/64)][S][64] scaled.
// =========================================================================
__device__ __forceinline__ float lo_part(float v) {
    return v - __bfloat162float(__float2bfloat16(v));
}

__global__ void __launch_bounds__(256) wgemm_kernel(
    const float* __restrict__ W, const float* __restrict__ X,
    const float* __restrict__ bias,
    const float* __restrict__ affA, const float* __restrict__ affD,
    float* __restrict__ outF, __nv_bfloat16* __restrict__ outB,
    int M, int S, int split, float outScale) {
    __shared__ __align__(16) __nv_bfloat16 As[64 * 32];
    __shared__ __align__(16) __nv_bfloat16 Bs[32 * 136];
    __shared__ __align__(16) float Cs[64 * 132];

    int tid = threadIdx.x, warp = tid >> 5;
    int m0 = blockIdx.x * 64;
    int s0 = blockIdx.y * 128;
    int z  = blockIdx.z;
    const float* Xb = X + (size_t)z * 256 * S;

    wmma::fragment<wmma::accumulator, 16, 16, 16, float> acc[2][2];
    #pragma unroll
    for (int i = 0; i < 2; i++)
        #pragma unroll
        for (int j = 0; j < 2; j++) wmma::fill_fragment(acc[i][j], 0.f);

    int wm = warp >> 2, wn = warp & 3;
    const int KT = split ? 768 : 256;

    for (int kt = 0; kt < KT; kt += 32) {
        int seg = kt >> 8;
        // ---- load A (W) 64x32 ----
        {
            int r = tid >> 2, kq = (tid & 3) * 8;
            int kk = (kt & 255) + kq;
            const float* wp = W + (size_t)(m0 + r) * 256 + kk;
            #pragma unroll
            for (int i = 0; i < 2; i++) {
                float4 w4 = *reinterpret_cast<const float4*>(wp + i * 4);
                if (split && seg == 1) {
                    w4.x = lo_part(w4.x); w4.y = lo_part(w4.y);
                    w4.z = lo_part(w4.z); w4.w = lo_part(w4.w);
                }
                *reinterpret_cast<__nv_bfloat162*>(&As[r * 32 + kq + i * 4]) =
                    __floats2bfloat162_rn(w4.x, w4.y);
                *reinterpret_cast<__nv_bfloat162*>(&As[r * 32 + kq + i * 4 + 2]) =
                    __floats2bfloat162_rn(w4.z, w4.w);
            }
        }
        // ---- load B (X) 32x128 ----
        {
            int kr = tid >> 3, sq = (tid & 7) * 16;
            int kk = (kt & 255) + kr;
            float aa = 1.f, dd = 0.f;
            if (affA) { aa = affA[z * 256 + kk]; dd = affD[z * 256 + kk]; }
            const float* xp = Xb + (size_t)kk * S + s0 + sq;
            #pragma unroll
            for (int i = 0; i < 4; i++) {
                float4 v = *reinterpret_cast<const float4*>(xp + i * 4);
                v.x = fmaf(aa, v.x, dd); v.y = fmaf(aa, v.y, dd);
                v.z = fmaf(aa, v.z, dd); v.w = fmaf(aa, v.w, dd);
                if (split && seg == 2) {
                    v.x = lo_part(v.x); v.y = lo_part(v.y);
                    v.z = lo_part(v.z); v.w = lo_part(v.w);
                }
                *reinterpret_cast<__nv_bfloat162*>(&Bs[kr * 136 + sq + i * 4]) =
                    __floats2bfloat162_rn(v.x, v.y);
                *reinterpret_cast<__nv_bfloat162*>(&Bs[kr * 136 + sq + i * 4 + 2]) =
                    __floats2bfloat162_rn(v.z, v.w);
            }
        }
        __syncthreads();
        #pragma unroll
        for (int ks = 0; ks < 2; ks++) {
            wmma::fragment<wmma::matrix_a, 16, 16, 16, __nv_bfloat16, wmma::row_major> a0, a1;
            wmma::load_matrix_sync(a0, &As[(wm * 32) * 32 + ks * 16], 32);
            wmma::load_matrix_sync(a1, &As[(wm * 32 + 16) * 32 + ks * 16], 32);
            wmma::fragment<wmma::matrix_b, 16, 16, 16, __nv_bfloat16, wmma::row_major> b0, b1;
            wmma::load_matrix_sync(b0, &Bs[(ks * 16) * 136 + wn * 32], 136);
            wmma::load_matrix_sync(b1, &Bs[(ks * 16) * 136 + wn * 32 + 16], 136);
            wmma::mma_sync(acc[0][0], a0, b0, acc[0][0]);
            wmma::mma_sync(acc[0][1], a0, b1, acc[0][1]);
            wmma::mma_sync(acc[1][0], a1, b0, acc[1][0]);
            wmma::mma_sync(acc[1][1], a1, b1, acc[1][1]);
        }
        __syncthreads();
    }

    // ---- epilogue through smem ----
    #pragma unroll
    for (int i = 0; i < 2; i++)
        #pragma unroll
        for (int j = 0; j < 2; j++)
            wmma::store_matrix_sync(&Cs[(wm * 32 + i * 16) * 132 + wn * 32 + j * 16],
                                    acc[i][j], 132, wmma::mem_row_major);
    __syncthreads();

    if (outF) {
        float* Ob = outF + (size_t)z * M * S;
        #pragma unroll
        for (int i = 0; i < 8; i++) {
            int idx = tid + i * 256;
            int r = idx >> 5, c4 = idx & 31;
            float bv = bias[m0 + r];
            float4 v = *reinterpret_cast<const float4*>(&Cs[r * 132 + c4 * 4]);
            v.x += bv; v.y += bv; v.z += bv; v.w += bv;
            *reinterpret_cast<float4*>(&Ob[(size_t)(m0 + r) * S + s0 + c4 * 4]) = v;
        }
    } else {
        int hb = m0 >> 6;
        __nv_bfloat16* base = outB + ((size_t)(z * (M >> 6) + hb) * S) * 64;
        #pragma unroll
        for (int i = 0; i < 32; i++) {
            int idx = tid + i * 256;
            int d = idx & 63, sl = idx >> 6;
            float v = (Cs[d * 132 + sl] + bias[m0 + d]) * outScale;
            base[(size_t)(s0 + sl) * 64 + d] = __float2bfloat16(v);
        }
    }
}

// =========================================================================
// Local windowed attention (fp32, unchanged)
// =========================================================================
__global__ void __launch_bounds__(64) local_attn_kernel(
    const float* __restrict__ qkv, const float* __restrict__ x, float* __restrict__ out) {
    __shared__ float Ks[64][64];
    __shared__ float Vs[64][64];
    int w = blockIdx.x, head = blockIdx.y, n = blockIdx.z;
    int tid = threadIdx.x;
    const float* qkvn = qkv + (size_t)n * 768 * SV;
    int wh = w >> 6, ww = (w >> 3) & 7, wd = w & 7;
    int base_s = ((wh * 4) * 32 + ww * 4) * 32 + wd * 4;

    for (int idx = tid; idx < 4096; idx += 64) {
        int t = idx & 63, hd = idx >> 6;
        int s = base_s + (t >> 4) * 1024 + ((t >> 2) & 3) * 32 + (t & 3);
        Ks[t][hd] = qkvn[(size_t)(256 + head * 64 + hd) * SV + s];
        Vs[t][hd] = qkvn[(size_t)(512 + head * 64 + hd) * SV + s];
    }
    int sr = base_s + (tid >> 4) * 1024 + ((tid >> 2) & 3) * 32 + (tid & 3);
    float q[64];
    #pragma unroll
    for (int hd = 0; hd < 64; hd++)
        q[hd] = qkvn[(size_t)(head * 64 + hd) * SV + sr] * SCALE_INV;
    __syncthreads();

    float sc[64];
    float m = -1e30f;
    for (int c = 0; c < 64; c++) {
        const float4* k4 = reinterpret_cast<const float4*>(Ks[c]);
        float s_ = 0.f;
        #pragma unroll
        for (int h = 0; h < 16; h++) {
            float4 kk = k4[h];
            s_ += q[4*h+0]*kk.x + q[4*h+1]*kk.y + q[4*h+2]*kk.z + q[4*h+3]*kk.w;
        }
        sc[c] = s_;
        m = fmaxf(m, s_);
    }
    float l = 0.f;
    #pragma unroll
    for (int c = 0; c < 64; c++) { sc[c] = __expf(sc[c] - m); l += sc[c]; }
    float inv = 1.f / l;

    float o[64];
    #pragma unroll
    for (int h = 0; h < 64; h++) o[h] = 0.f;
    for (int t = 0; t < 64; t++) {
        float p = sc[t];
        const float4* v4 = reinterpret_cast<const float4*>(Vs[t]);
        #pragma unroll
        for (int h = 0; h < 16; h++) {
            float4 vv = v4[h];
            o[4*h+0] += p*vv.x; o[4*h+1] += p*vv.y; o[4*h+2] += p*vv.z; o[4*h+3] += p*vv.w;
        }
    }
    const float* xn = x   + ((size_t)n * CH + head * 64) * SV;
    float* on       = out + ((size_t)n * CH + head * 64) * SV;
    #pragma unroll
    for (int hd = 0; hd < 64; hd++)
        on[(size_t)hd * SV + sr] = xn[(size_t)hd * SV + sr] + o[hd] * inv;
}

// =========================================================================
// Global attention (wmma bf16, online softmax): 128 queries/block x 512 keys
// =========================================================================
#define GA_SMEM 196096

__global__ void __launch_bounds__(256) gattn_kernel(
    const __nv_bfloat16* __restrict__ q2T, const __nv_bfloat16* __restrict__ kvT,
    const float* __restrict__ attn, float* __restrict__ g) {
    extern __shared__ __align__(16) char sm[];
    __nv_bfloat16* Qs = (__nv_bfloat16*)sm;          // [128][72]
    __nv_bfloat16* Ks = Qs + 128 * 72;               // [128][72]
    __nv_bfloat16* Vs = Ks + 128 * 72;               // [128][72]
    __nv_bfloat16* Ps = Vs + 128 * 72;               // [128][136]
    float* Sf   = (float*)(Ps + 128 * 136);          // [128][132]
    float* Of   = Sf + 128 * 132;                    // [128][72]
    float* mrow = Of + 128 * 72;
    float* lrow = mrow + 128;
    float* crow = lrow + 128;

    int tid = threadIdx.x, warp = tid >> 5;
    int h = blockIdx.y, n = blockIdx.z;
    int s0 = blockIdx.x * 128;

    const uint4* Qg = (const uint4*)(q2T + ((size_t)(n * 4 + h) * SV + s0) * 64);
    const uint4* Kg = (const uint4*)(kvT + ((size_t)(n * 8 + h) * 512) * 64);
    const uint4* Vg = (const uint4*)(kvT + ((size_t)(n * 8 + 4 + h) * 512) * 64);

    #pragma unroll
    for (int i = 0; i < 4; i++) {
        int idx = tid + i * 256;
        int r = idx >> 3, c = idx & 7;
        ((uint4*)(Qs + r * 72))[c] = Qg[r * 8 + c];
    }
    for (int i = tid; i < 128 * 72; i += 256) Of[i] = 0.f;
    if (tid < 128) { mrow[tid] = -1e30f; lrow[tid] = 0.f; }
    __syncthreads();

    for (int ch = 0; ch < 4; ch++) {
        // stage K/V chunk
        #pragma unroll
        for (int i = 0; i < 4; i++) {
            int idx = tid + i * 256;
            int r = idx >> 3, c = idx & 7;
            ((uint4*)(Ks + r * 72))[c] = Kg[(ch * 128 + r) * 8 + c];
            ((uint4*)(Vs + r * 72))[c] = Vg[(ch * 128 + r) * 8 + c];
        }
        __syncthreads();

        // ---- S = Q @ K^T  (128x128) ----
        {
            int wm = warp >> 2, wn = warp & 3;     // 2(M) x 4(N), warp tile 64x32
            wmma::fragment<wmma::accumulator, 16, 16, 16, float> acc[4][2];
            #pragma unroll
            for (int i = 0; i < 4; i++)
                #pragma unroll
                for (int j = 0; j < 2; j++) wmma::fill_fragment(acc[i][j], 0.f);
            #pragma unroll
            for (int kd = 0; kd < 4; kd++) {
                wmma::fragment<wmma::matrix_a, 16, 16, 16, __nv_bfloat16, wmma::row_major> af[4];
                #pragma unroll
                for (int i = 0; i < 4; i++)
                    wmma::load_matrix_sync(af[i], Qs + (wm * 64 + i * 16) * 72 + kd * 16, 72);
                wmma::fragment<wmma::matrix_b, 16, 16, 16, __nv_bfloat16, wmma::col_major> bf[2];
                #pragma unroll
                for (int j = 0; j < 2; j++)
                    wmma::load_matrix_sync(bf[j], Ks + (wn * 32 + j * 16) * 72 + kd * 16, 72);
                #pragma unroll
                for (int i = 0; i < 4; i++)
                    #pragma unroll
                    for (int j = 0; j < 2; j++)
                        wmma::mma_sync(acc[i][j], af[i], bf[j], acc[i][j]);
            }
            #pragma unroll
            for (int i = 0; i < 4; i++)
                #pragma unroll
                for (int j = 0; j < 2; j++)
                    wmma::store_matrix_sync(Sf + (wm * 64 + i * 16) * 132 + wn * 32 + j * 16,
                                            acc[i][j], 132, wmma::mem_row_major);
        }
        __syncthreads();

        // ---- online softmax over this chunk ----
        {
            int r = tid >> 1, half = tid & 1;
            const float* srow = Sf + r * 132 + half * 64;
            float cm = -1e30f;
            #pragma unroll
            for (int j = 0; j < 64; j++) cm = fmaxf(cm, srow[j]);
            cm = fmaxf(cm, __shfl_xor_sync(0xffffffffu, cm, 1));
            float mold = mrow[r];
            float mnew = fmaxf(mold, cm);
            float ls = 0.f;
            __nv_bfloat16* prow = Ps + r * 136 + half * 64;
            #pragma unroll
            for (int j = 0; j < 64; j++) {
                float p = __expf(srow[j] - mnew);
                ls += p;
                prow[j] = __float2bfloat16(p);
            }
            ls += __shfl_xor_sync(0xffffffffu, ls, 1);
            if (half == 0) {
                float corr = __expf(mold - mnew);
                lrow[r] = lrow[r] * corr + ls;
                mrow[r] = mnew;
                crow[r] = corr;
            }
        }
        __syncthreads();

        // rescale O
        for (int i = tid; i < 128 * 64; i += 256) {
            int r = i >> 6, d = i & 63;
            Of[r * 72 + d] *= crow[r];
        }
        __syncthreads();

        // ---- O += P @ V ----
        {
            int pm = warp >> 1, pn = warp & 1;     // 4(M) x 2(N), warp tile 32x32
            wmma::fragment<wmma::accumulator, 16, 16, 16, float> acc2[2][2];
            #pragma unroll
            for (int i = 0; i < 2; i++)
                #pragma unroll
                for (int j = 0; j < 2; j++)
                    wmma::load_matrix_sync(acc2[i][j],
                        Of + (pm * 32 + i * 16) * 72 + pn * 32 + j * 16, 72, wmma::mem_row_major);
            #pragma unroll
            for (int kk = 0; kk < 8; kk++) {
                wmma::fragment<wmma::matrix_a, 16, 16, 16, __nv_bfloat16, wmma::row_major> af[2];
                #pragma unroll
                for (int i = 0; i < 2; i++)
                    wmma::load_matrix_sync(af[i], Ps + (pm * 32 + i * 16) * 136 + kk * 16, 136);
                wmma::fragment<wmma::matrix_b, 16, 16, 16, __nv_bfloat16, wmma::row_major> bf[2];
                #pragma unroll
                for (int j = 0; j < 2; j++)
                    wmma::load_matrix_sync(bf[j], Vs + (kk * 16) * 72 + pn * 32 + j * 16, 72);
                #pragma unroll
                for (int i = 0; i < 2; i++)
                    #pragma unroll
                    for (int j = 0; j < 2; j++)
                        wmma::mma_sync(acc2[i][j], af[i], bf[j], acc2[i][j]);
            }
            #pragma unroll
            for (int i = 0; i < 2; i++)
                #pragma unroll
                for (int j = 0; j < 2; j++)
                    wmma::store_matrix_sync(Of + (pm * 32 + i * 16) * 72 + pn * 32 + j * 16,
                                            acc2[i][j], 72, wmma::mem_row_major);
        }
        __syncthreads();
    }

    // finalize: g = O / l + attn
    #pragma unroll
    for (int i = 0; i < 32; i++) {
        int idx = tid + i * 256;
        int r = idx & 127, d = idx >> 7;
        float v = Of[r * 72 + d] / lrow[r];
        size_t gi = ((size_t)(n * 256 + h * 64 + d)) * SV + s0 + r;
        g[gi] = v + attn[gi];
    }
}

// =========================================================================
// host launch
// =========================================================================
extern "C" void kernel_launch(void* const* d_in, const int* in_sizes, int n_in,
                              void* d_out, int out_size) {
    const float* x      = (const float*)d_in[0];
    const float* qkv_w  = (const float*)d_in[1];
    const float* qkv_b  = (const float*)d_in[2];
    const float* norm_w = (const float*)d_in[3];
    const float* norm_b = (const float*)d_in[4];
    const float* anorm_w= (const float*)d_in[5];
    const float* anorm_b= (const float*)d_in[6];
    const float* dnorm_w= (const float*)d_in[7];
    const float* dnorm_b= (const float*)d_in[8];
    const float* q_w    = (const float*)d_in[9];
    const float* q_b    = (const float*)d_in[10];
    const float* kv_w   = (const float*)d_in[11];
    const float* kv_b   = (const float*)d_in[12];
    const float* proj_w = (const float*)d_in[13];
    const float* proj_b = (const float*)d_in[14];
    float* out = (float*)d_out;

    float *qkv, *attn, *gg, *pooled, *part, *stats, *aff;
    __nv_bfloat16 *q2T, *kvT;
    cudaGetSymbolAddress((void**)&qkv,    g_qkv);
    cudaGetSymbolAddress((void**)&attn,   g_attn);
    cudaGetSymbolAddress((void**)&gg,     g_g);
    cudaGetSymbolAddress((void**)&pooled, g_pooled);
    cudaGetSymbolAddress((void**)&q2T,    g_q2T);
    cudaGetSymbolAddress((void**)&kvT,    g_kvT);
    cudaGetSymbolAddress((void**)&part,   g_part);
    cudaGetSymbolAddress((void**)&stats,  g_stats);
    cudaGetSymbolAddress((void**)&aff,    g_aff);

    static bool attr_set = false;
    if (!attr_set) {
        cudaFuncSetAttribute(gattn_kernel, cudaFuncAttributeMaxDynamicSharedMemorySize, GA_SMEM);
        attr_set = true;
    }

    float* A0 = aff;        float* D0 = aff + 512;
    float* A1 = aff + 1024; float* D1 = aff + 1536;
    float* A2 = aff + 2048; float* D2 = aff + 2560;

    // GroupNorm(x) -> affine folded into qkv GEMM
    reduce1_kernel<<<dim3(512, NB), 256>>>(x, 256L * SV, part);
    reduce2_kernel<<<NB, 256>>>(part, 512, stats);
    make_affine_kernel<<<NB, 256>>>(stats, norm_w, norm_b, A0, D0, 1.f / (256.f * 32768.f));

    // qkv conv (bf16 tensor cores), fp32 out for local attention
    wgemm_kernel<<<dim3(12, 256, NB), 256>>>(qkv_w, x, qkv_b, A0, D0,
                                             qkv, nullptr, 768, (int)SV, 0, 1.f);

    // local windowed attention: attn = x + attn_out
    local_attn_kernel<<<dim3(512, NH, NB), 64>>>(qkv, x, attn);

    // GroupNorm(x + attn) in place
    reduce1_kernel<<<dim3(512, NB), 256>>>(attn, 256L * SV, part);
    reduce2_kernel<<<NB, 256>>>(part, 512, stats);
    make_affine_kernel<<<NB, 256>>>(stats, anorm_w, anorm_b, A1, D1, 1.f / (256.f * 32768.f));
    apply_norm_kernel<<<16384, 256>>>(attn, A1, D1);

    // pool + ds GroupNorm affine + kv conv -> transposed bf16 K/V
    pool_kernel<<<1024, 256>>>(attn, pooled);
    reduce1_kernel<<<dim3(32, NB), 256>>>(pooled, 256L * 512, part);
    reduce2_kernel<<<NB, 256>>>(part, 32, stats);
    make_affine_kernel<<<NB, 256>>>(stats, dnorm_w, dnorm_b, A2, D2, 1.f / (256.f * 512.f));
    wgemm_kernel<<<dim3(8, 4, NB), 256>>>(kv_w, pooled, kv_b, A2, D2,
                                          nullptr, kvT, 512, 512, 0, 1.f);

    // q conv -> transposed bf16 Q (pre-scaled by 1/16)
    wgemm_kernel<<<dim3(4, 256, NB), 256>>>(q_w, attn, q_b, nullptr, nullptr,
                                            nullptr, q2T, 256, (int)SV, 0, SCALE_INV);

    // global attention + residual (wmma)
    gattn_kernel<<<dim3(256, NH, NB), 256, GA_SMEM>>>(q2T, kvT, attn, gg);

    // final projection: 3xBF16 split for near-fp32 accuracy
    wgemm_kernel<<<dim3(4, 256, NB), 256>>>(proj_w, gg, proj_b, nullptr, nullptr,
                                            out, nullptr, 256, (int)SV, 1, 1.f);
}

// round 4
// speedup vs baseline: 2.6229x; 1.4931x over previous
#include <cuda_runtime.h>
#include <cuda_bf16.h>
#include <mma.h>
#include <math.h>
#include <stdint.h>

using namespace nvcuda;

#define NB 2
#define CH 256
#define SV 32768L
#define NH 4
#define HD 64
#define SCALE_INV 0.0625f
#define EPS 1e-6f

// pack two floats -> bf16x2 bits
__device__ __forceinline__ unsigned pack2(float a, float b) {
    __nv_bfloat162 t = __floats2bfloat162_rn(a, b);
    return *reinterpret_cast<unsigned*>(&t);
}

// ---------------- scratch ----------------
__device__ __align__(16) float g_attn  [NB * 256L * SV];
__device__ __align__(16) float g_pooled[NB * 256 * 512];
__device__ __align__(16) __nv_bfloat16 g_xnB   [NB * 256L * SV];
__device__ __align__(16) __nv_bfloat16 g_qkvB  [NB * 768L * SV];
__device__ __align__(16) __nv_bfloat16 g_attnB [NB * 256L * SV];
__device__ __align__(16) __nv_bfloat16 g_ghi   [NB * 256L * SV];
__device__ __align__(16) __nv_bfloat16 g_glo   [NB * 256L * SV];
__device__ __align__(16) __nv_bfloat16 g_pooledB[NB * 256 * 512];
__device__ __align__(16) __nv_bfloat16 g_q2T   [NB * 4L * SV * 64];
__device__ __align__(16) __nv_bfloat16 g_kvT   [NB * 8L * 512 * 64];
__device__ __align__(16) __nv_bfloat16 g_WqkvB [768 * 256];
__device__ __align__(16) __nv_bfloat16 g_WqB   [256 * 256];
__device__ __align__(16) __nv_bfloat16 g_WkvB  [512 * 256];
__device__ __align__(16) __nv_bfloat16 g_WprojB[256 * 768];
__device__ float g_part [NB * 512 * 2];
__device__ float g_stats[NB * 2];
__device__ float g_aff  [6 * NB * 256];

// ---------------- cp.async helpers ----------------
__device__ __forceinline__ void cp16(void* dst, const void* src) {
    unsigned d = (unsigned)__cvta_generic_to_shared(dst);
    asm volatile("cp.async.cg.shared.global [%0], [%1], 16;\n" :: "r"(d), "l"(src));
}
#define CP_COMMIT asm volatile("cp.async.commit_group;\n" ::: "memory")
#define CP_WAIT1  asm volatile("cp.async.wait_group 1;\n" ::: "memory")
#define CP_WAIT0  asm volatile("cp.async.wait_group 0;\n" ::: "memory")

// =========================================================================
// reductions / affine / elementwise
// =========================================================================
__global__ void reduce1_kernel(const float* __restrict__ buf, long per, float* __restrict__ part) {
    int n = blockIdx.y;
    const float* p = buf + (size_t)n * per;
    float s = 0.f, ss = 0.f;
    for (long i = (long)blockIdx.x * blockDim.x + threadIdx.x; i < per;
         i += (long)gridDim.x * blockDim.x) {
        float v = p[i];
        s += v; ss += v * v;
    }
    for (int o = 16; o; o >>= 1) {
        s  += __shfl_down_sync(0xffffffffu, s, o);
        ss += __shfl_down_sync(0xffffffffu, ss, o);
    }
    __shared__ float sh[64];
    int w = threadIdx.x >> 5;
    if ((threadIdx.x & 31) == 0) { sh[w] = s; sh[32 + w] = ss; }
    __syncthreads();
    if (threadIdx.x < 32) {
        int nw = blockDim.x >> 5;
        s  = (threadIdx.x < nw) ? sh[threadIdx.x]      : 0.f;
        ss = (threadIdx.x < nw) ? sh[32 + threadIdx.x] : 0.f;
        for (int o = 16; o; o >>= 1) {
            s  += __shfl_down_sync(0xffffffffu, s, o);
            ss += __shfl_down_sync(0xffffffffu, ss, o);
        }
        if (threadIdx.x == 0) {
            part[((size_t)n * gridDim.x + blockIdx.x) * 2 + 0] = s;
            part[((size_t)n * gridDim.x + blockIdx.x) * 2 + 1] = ss;
        }
    }
}

__global__ void reduce2_kernel(const float* __restrict__ part, int nb, float* __restrict__ stats) {
    int n = blockIdx.x;
    float s = 0.f, ss = 0.f;
    for (int i = threadIdx.x; i < nb; i += blockDim.x) {
        s  += part[((size_t)n * nb + i) * 2 + 0];
        ss += part[((size_t)n * nb + i) * 2 + 1];
    }
    for (int o = 16; o; o >>= 1) {
        s  += __shfl_down_sync(0xffffffffu, s, o);
        ss += __shfl_down_sync(0xffffffffu, ss, o);
    }
    __shared__ float sh[64];
    int w = threadIdx.x >> 5;
    if ((threadIdx.x & 31) == 0) { sh[w] = s; sh[32 + w] = ss; }
    __syncthreads();
    if (threadIdx.x < 32) {
        int nw = blockDim.x >> 5;
        s  = (threadIdx.x < nw) ? sh[threadIdx.x]      : 0.f;
        ss = (threadIdx.x < nw) ? sh[32 + threadIdx.x] : 0.f;
        for (int o = 16; o; o >>= 1) {
            s  += __shfl_down_sync(0xffffffffu, s, o);
            ss += __shfl_down_sync(0xffffffffu, ss, o);
        }
        if (threadIdx.x == 0) { stats[n * 2] = s; stats[n * 2 + 1] = ss; }
    }
}

__global__ void make_affine_kernel(const float* __restrict__ stats,
                                   const float* __restrict__ w, const float* __restrict__ b,
                                   float* __restrict__ a, float* __restrict__ d, float inv_cnt) {
    int c = threadIdx.x;
    int n = blockIdx.x;
    float mean = stats[n * 2] * inv_cnt;
    float var  = stats[n * 2 + 1] * inv_cnt - mean * mean;
    float rstd = rsqrtf(var + EPS);
    a[n * CH + c] = w[c] * rstd;
    d[n * CH + c] = b[c] - mean * rstd * w[c];
}

// x -> bf16(a*x+d)
__global__ void convert_x_kernel(const float* __restrict__ x,
                                 const float* __restrict__ a, const float* __restrict__ d,
                                 __nv_bfloat16* __restrict__ out) {
    size_t i4 = (size_t)blockIdx.x * blockDim.x + threadIdx.x;
    int c = (int)((i4 >> 13) & 255);
    int n = (int)(i4 >> 21);
    float aa = a[n * CH + c], dd = d[n * CH + c];
    float4 v = reinterpret_cast<const float4*>(x)[i4];
    uint2 r;
    r.x = pack2(fmaf(aa, v.x, dd), fmaf(aa, v.y, dd));
    r.y = pack2(fmaf(aa, v.z, dd), fmaf(aa, v.w, dd));
    reinterpret_cast<uint2*>(out)[i4] = r;
}

// attn = a*attn+d in place (fp32) + bf16 copy
__global__ void apply_norm2_kernel(float* __restrict__ buf,
                                   const float* __restrict__ a, const float* __restrict__ d,
                                   __nv_bfloat16* __restrict__ outB) {
    size_t i4 = (size_t)blockIdx.x * blockDim.x + threadIdx.x;
    int c = (int)((i4 >> 13) & 255);
    int n = (int)(i4 >> 21);
    float aa = a[n * CH + c], dd = d[n * CH + c];
    float4 v = reinterpret_cast<float4*>(buf)[i4];
    v.x = fmaf(aa, v.x, dd); v.y = fmaf(aa, v.y, dd);
    v.z = fmaf(aa, v.z, dd); v.w = fmaf(aa, v.w, dd);
    reinterpret_cast<float4*>(buf)[i4] = v;
    uint2 r;
    r.x = pack2(v.x, v.y);
    r.y = pack2(v.z, v.w);
    reinterpret_cast<uint2*>(outB)[i4] = r;
}

__global__ void pool_kernel(const float* __restrict__ attn, float* __restrict__ pooled) {
    int idx = blockIdx.x * blockDim.x + threadIdx.x;
    if (idx >= NB * 256 * 512) return;
    int p = idx & 511, c = (idx >> 9) & 255, n = idx >> 17;
    int ph = p >> 6, pw = (p >> 3) & 7, pd = p & 7;
    const float* base = attn + ((size_t)n * CH + c) * SV;
    float s = 0.f;
    #pragma unroll
    for (int i = 0; i < 4; i++)
        #pragma unroll
        for (int j = 0; j < 4; j++)
            #pragma unroll
            for (int k = 0; k < 4; k++)
                s += base[((ph * 4 + i) * 32 + (pw * 4 + j)) * 32 + (pd * 4 + k)];
    pooled[((size_t)n * CH + c) * 512 + p] = s * (1.f / 64.f);
}

__global__ void convert_pooled_kernel(const float* __restrict__ pooled,
                                      const float* __restrict__ a, const float* __restrict__ d,
                                      __nv_bfloat16* __restrict__ out) {
    size_t i4 = (size_t)blockIdx.x * blockDim.x + threadIdx.x;   // 65536 groups
    int c = (int)((i4 >> 7) & 255);
    int n = (int)(i4 >> 15);
    float aa = a[n * CH + c], dd = d[n * CH + c];
    float4 v = reinterpret_cast<const float4*>(pooled)[i4];
    uint2 r;
    r.x = pack2(fmaf(aa, v.x, dd), fmaf(aa, v.y, dd));
    r.y = pack2(fmaf(aa, v.z, dd), fmaf(aa, v.w, dd));
    reinterpret_cast<uint2*>(out)[i4] = r;
}

// all weight buffers in one pass; proj gets [hiW | loW | hiW] along K
__global__ void convert_weights_kernel(
    const float* __restrict__ qkv_w, const float* __restrict__ q_w,
    const float* __restrict__ kv_w, const float* __restrict__ proj_w,
    __nv_bfloat16* __restrict__ Wqkv, __nv_bfloat16* __restrict__ Wq,
    __nv_bfloat16* __restrict__ Wkv, __nv_bfloat16* __restrict__ Wproj) {
    int idx = blockIdx.x * blockDim.x + threadIdx.x;
    const int T1 = 768 * 256, T2 = T1 + 256 * 256, T3 = T2 + 512 * 256, T4 = T3 + 256 * 768;
    if (idx < T1) {
        Wqkv[idx] = __float2bfloat16(qkv_w[idx]);
    } else if (idx < T2) {
        int j = idx - T1; Wq[j] = __float2bfloat16(q_w[j]);
    } else if (idx < T3) {
        int j = idx - T2; Wkv[j] = __float2bfloat16(kv_w[j]);
    } else if (idx < T4) {
        int j = idx - T3;
        int m = j / 768, k = j % 768;
        float v = proj_w[m * 256 + (k & 255)];
        __nv_bfloat16 hi = __float2bfloat16(v);
        if (k >= 256 && k < 512) hi = __float2bfloat16(v - __bfloat162float(hi));
        Wproj[j] = hi;
    }
}

// =========================================================================
// wgemm2: C[m,s] = sum_k A[m,k]*B[k,s], A bf16 [M][KT], B bf16 [z][256][S]
// (proj: logical K=768, B seg0/1 = B0(hi), seg2 = B1(lo))
// MODE 0: fp32 out[z][M][S] + bias
// MODE 1: bf16 T-layout out[(z*(M/64)+m0/64)][S][64] * qScale + bias
// MODE 2: bf16 qkv window layout, q (sel 0) scaled by qScale
// BM=64, BN=128, BK=32, 256 threads, warp tile 32x32, 2-stage cp.async
// =========================================================================
#define WG_SMEM 33792

template<int MODE>
__global__ void __launch_bounds__(256) wgemm2_kernel(
    const __nv_bfloat16* __restrict__ A,
    const __nv_bfloat16* __restrict__ B0, const __nv_bfloat16* __restrict__ B1,
    const float* __restrict__ bias,
    float* __restrict__ outF, __nv_bfloat16* __restrict__ outB,
    int M, int S, int KT, float qScale) {
    extern __shared__ __align__(16) char dsm[];
    __nv_bfloat16* As = (__nv_bfloat16*)dsm;             // [2][64*40]
    __nv_bfloat16* Bs = (__nv_bfloat16*)(dsm + 10240);   // [2][32*136]
    float* Cs = (float*)dsm;                             // [64][132] (post-loop)

    int tid = threadIdx.x, warp = tid >> 5;
    int wm = warp >> 2, wn = warp & 3;
    int m0 = blockIdx.x * 64;
    int s0 = blockIdx.y * 128;
    int z  = blockIdx.z;

    const __nv_bfloat16* Bb0 = B0 + (size_t)z * 256 * S;
    const __nv_bfloat16* Bb1 = B1 + (size_t)z * 256 * S;

    wmma::fragment<wmma::accumulator, 16, 16, 16, float> acc[2][2];
    #pragma unroll
    for (int i = 0; i < 2; i++)
        #pragma unroll
        for (int j = 0; j < 2; j++) wmma::fill_fragment(acc[i][j], 0.f);

    const int NIT = KT >> 5;

    auto prefetch = [&](int it, int buf) {
        int ktL = it * 32;
        {
            int r = tid >> 2, q = tid & 3;
            cp16(As + buf * 2560 + r * 40 + q * 8,
                 A + (size_t)(m0 + r) * KT + ktL + q * 8);
        }
        const __nv_bfloat16* Bp = (ktL < 512) ? Bb0 : Bb1;
        int krow = ktL & 255;
        #pragma unroll
        for (int i = 0; i < 2; i++) {
            int c = tid + i * 256;
            int r = c >> 4, q = c & 15;
            cp16(Bs + buf * 4352 + r * 136 + q * 8,
                 Bp + (size_t)(krow + r) * S + s0 + q * 8);
        }
    };

    prefetch(0, 0);
    CP_COMMIT;

    for (int it = 0; it < NIT; it++) {
        if (it + 1 < NIT) {
            prefetch(it + 1, (it + 1) & 1);
            CP_COMMIT;
            CP_WAIT1;
        } else {
            CP_WAIT0;
        }
        __syncthreads();
        int buf = it & 1;
        #pragma unroll
        for (int ks = 0; ks < 2; ks++) {
            wmma::fragment<wmma::matrix_a, 16, 16, 16, __nv_bfloat16, wmma::row_major> af[2];
            #pragma unroll
            for (int i = 0; i < 2; i++)
                wmma::load_matrix_sync(af[i], As + buf * 2560 + (wm * 32 + i * 16) * 40 + ks * 16, 40);
            wmma::fragment<wmma::matrix_b, 16, 16, 16, __nv_bfloat16, wmma::row_major> bf[2];
            #pragma unroll
            for (int j = 0; j < 2; j++)
                wmma::load_matrix_sync(bf[j], Bs + buf * 4352 + (ks * 16) * 136 + wn * 32 + j * 16, 136);
            #pragma unroll
            for (int i = 0; i < 2; i++)
                #pragma unroll
                for (int j = 0; j < 2; j++)
                    wmma::mma_sync(acc[i][j], af[i], bf[j], acc[i][j]);
        }
        __syncthreads();
    }

    // stage accumulators
    #pragma unroll
    for (int i = 0; i < 2; i++)
        #pragma unroll
        for (int j = 0; j < 2; j++)
            wmma::store_matrix_sync(Cs + (wm * 32 + i * 16) * 132 + wn * 32 + j * 16,
                                    acc[i][j], 132, wmma::mem_row_major);
    __syncthreads();

    if (MODE == 0) {
        float* Ob = outF + ((size_t)z * M + m0) * S;
        #pragma unroll
        for (int it = 0; it < 8; it++) {
            int idx = tid + it * 256;
            int r = idx >> 5, c4 = idx & 31;
            float bv = bias[m0 + r];
            float4 v = *reinterpret_cast<const float4*>(&Cs[r * 132 + c4 * 4]);
            v.x += bv; v.y += bv; v.z += bv; v.w += bv;
            *reinterpret_cast<float4*>(&Ob[(size_t)r * S + s0 + c4 * 4]) = v;
        }
    } else {
        float sc = qScale;
        __nv_bfloat16* base;
        if (MODE == 1) {
            base = outB + ((size_t)(z * (M >> 6) + (m0 >> 6)) * S + s0) * 64;
        } else {
            int sel = m0 >> 8, head = (m0 >> 6) & 3;
            if (sel != 0) sc = 1.f;
            base = outB + (((size_t)(z * 3 + sel) * 4 + head) * 512) * 4096;
        }
        #pragma unroll
        for (int it = 0; it < 4; it++) {
            int idx = tid + it * 256;
            int sl = idx & 127, dg = idx >> 7;
            float f[8];
            #pragma unroll
            for (int e = 0; e < 8; e++)
                f[e] = (Cs[(dg * 8 + e) * 132 + sl] + bias[m0 + dg * 8 + e]) * sc;
            uint4 u;
            u.x = pack2(f[0], f[1]);
            u.y = pack2(f[2], f[3]);
            u.z = pack2(f[4], f[5]);
            u.w = pack2(f[6], f[7]);
            size_t off;
            if (MODE == 1) {
                off = (size_t)sl * 64 + dg * 8;
            } else {
                int s = s0 + sl;
                int d5 = s & 31, w5 = (s >> 5) & 31, h5 = s >> 10;
                int window = ((h5 >> 2) * 8 + (w5 >> 2)) * 8 + (d5 >> 2);
                int token  = (((h5 & 3) * 4 + (w5 & 3)) * 4 + (d5 & 3));
                off = (size_t)window * 4096 + token * 64 + dg * 8;
            }
            *reinterpret_cast<uint4*>(base + off) = u;
        }
    }
}

// =========================================================================
// Local windowed attention (wmma): block per (window, head, n), 128 thr
// =========================================================================
__global__ void __launch_bounds__(128) local_attn_w_kernel(
    const __nv_bfloat16* __restrict__ qkvB, const float* __restrict__ x,
    float* __restrict__ attn) {
    __shared__ __align__(16) __nv_bfloat16 QP[64 * 72];  // Q, then P
    __shared__ __align__(16) __nv_bfloat16 Ks[64 * 72];
    __shared__ __align__(16) __nv_bfloat16 Vs[64 * 72];
    __shared__ __align__(16) float Sf[64 * 68];
    __shared__ float linv[64];

    int w = blockIdx.x, head = blockIdx.y, n = blockIdx.z;
    int tid = threadIdx.x, warp = tid >> 5;

    size_t base = (((size_t)(n * 3) * 4 + head) * 512 + w) * 4096;
    size_t step = (size_t)4 * 512 * 4096;
    const uint4* Qg = (const uint4*)(qkvB + base);
    const uint4* Kg = (const uint4*)(qkvB + base + step);
    const uint4* Vg = (const uint4*)(qkvB + base + 2 * step);

    #pragma unroll
    for (int i = 0; i < 4; i++) {
        int c = tid + i * 128;
        int r = c >> 3, q = c & 7;
        ((uint4*)(QP + r * 72))[q] = Qg[c];
        ((uint4*)(Ks + r * 72))[q] = Kg[c];
        ((uint4*)(Vs + r * 72))[q] = Vg[c];
    }
    __syncthreads();

    // S = Q @ K^T (Q pre-scaled by 1/16 at qkv epilogue)
    {
        int m = warp * 16;
        wmma::fragment<wmma::accumulator, 16, 16, 16, float> acc[4];
        #pragma unroll
        for (int j = 0; j < 4; j++) wmma::fill_fragment(acc[j], 0.f);
        #pragma unroll
        for (int kd = 0; kd < 4; kd++) {
            wmma::fragment<wmma::matrix_a, 16, 16, 16, __nv_bfloat16, wmma::row_major> af;
            wmma::load_matrix_sync(af, QP + m * 72 + kd * 16, 72);
            #pragma unroll
            for (int j = 0; j < 4; j++) {
                wmma::fragment<wmma::matrix_b, 16, 16, 16, __nv_bfloat16, wmma::col_major> bf;
                wmma::load_matrix_sync(bf, Ks + (j * 16) * 72 + kd * 16, 72);
                wmma::mma_sync(acc[j], af, bf, acc[j]);
            }
        }
        #pragma unroll
        for (int j = 0; j < 4; j++)
            wmma::store_matrix_sync(Sf + m * 68 + j * 16, acc[j], 68, wmma::mem_row_major);
    }
    __syncthreads();

    // softmax (full 64 keys), P -> QP (bf16)
    {
        int r = tid >> 1, hf = tid & 1;
        const float* srow = Sf + r * 68 + hf * 32;
        float mx = -1e30f;
        #pragma unroll
        for (int j = 0; j < 32; j++) mx = fmaxf(mx, srow[j]);
        mx = fmaxf(mx, __shfl_xor_sync(0xffffffffu, mx, 1));
        float ls = 0.f;
        __nv_bfloat16* prow = QP + r * 72 + hf * 32;
        #pragma unroll
        for (int j = 0; j < 32; j++) {
            float p = __expf(srow[j] - mx);
            ls += p;
            prow[j] = __float2bfloat16(p);
        }
        ls += __shfl_xor_sync(0xffffffffu, ls, 1);
        if (hf == 0) linv[r] = 1.f / ls;
    }
    __syncthreads();

    // O = P @ V -> Sf
    {
        int m = warp * 16;
        wmma::fragment<wmma::accumulator, 16, 16, 16, float> acc[4];
        #pragma unroll
        for (int j = 0; j < 4; j++) wmma::fill_fragment(acc[j], 0.f);
        #pragma unroll
        for (int kk = 0; kk < 4; kk++) {
            wmma::fragment<wmma::matrix_a, 16, 16, 16, __nv_bfloat16, wmma::row_major> af;
            wmma::load_matrix_sync(af, QP + m * 72 + kk * 16, 72);
            #pragma unroll
            for (int j = 0; j < 4; j++) {
                wmma::fragment<wmma::matrix_b, 16, 16, 16, __nv_bfloat16, wmma::row_major> bf;
                wmma::load_matrix_sync(bf, Vs + (kk * 16) * 72 + j * 16, 72);
                wmma::mma_sync(acc[j], af, bf, acc[j]);
            }
        }
        #pragma unroll
        for (int j = 0; j < 4; j++)
            wmma::store_matrix_sync(Sf + m * 68 + j * 16, acc[j], 68, wmma::mem_row_major);
    }
    __syncthreads();

    // attn = x + O/l  (float4 over 4 consecutive tokens per dim)
    int wh = w >> 6, ww = (w >> 3) & 7, wd = w & 7;
    int base_s = wh * 4096 + ww * 128 + wd * 4;
    int chb = n * 256 + head * 64;
    #pragma unroll
    for (int it = 0; it < 8; it++) {
        int idx = tid + it * 128;
        int d = idx >> 4, tg = idx & 15;
        int i_ = tg >> 2, j_ = tg & 3;
        int s = base_s + i_ * 1024 + j_ * 32;
        int t0 = tg * 4;
        size_t g = ((size_t)(chb + d)) * SV + s;
        float4 xv = *reinterpret_cast<const float4*>(x + g);
        float4 ov;
        ov.x = fmaf(Sf[(t0 + 0) * 68 + d], linv[t0 + 0], xv.x);
        ov.y = fmaf(Sf[(t0 + 1) * 68 + d], linv[t0 + 1], xv.y);
        ov.z = fmaf(Sf[(t0 + 2) * 68 + d], linv[t0 + 2], xv.z);
        ov.w = fmaf(Sf[(t0 + 3) * 68 + d], linv[t0 + 3], xv.w);
        *reinterpret_cast<float4*>(attn + g) = ov;
    }
}

// =========================================================================
// Global attention (wmma, online softmax) -> bf16 hi/lo for proj
// =========================================================================
#define GA_SMEM 196096

__global__ void __launch_bounds__(256) gattn_kernel(
    const __nv_bfloat16* __restrict__ q2T, const __nv_bfloat16* __restrict__ kvT,
    const float* __restrict__ attn,
    __nv_bfloat16* __restrict__ ghi, __nv_bfloat16* __restrict__ glo) {
    extern __shared__ __align__(16) char sm[];
    __nv_bfloat16* Qs = (__nv_bfloat16*)sm;          // [128][72]
    __nv_bfloat16* Ks = Qs + 128 * 72;
    __nv_bfloat16* Vs = Ks + 128 * 72;
    __nv_bfloat16* Ps = Vs + 128 * 72;               // [128][136]
    float* Sf   = (float*)(Ps + 128 * 136);          // [128][132]
    float* Of   = Sf + 128 * 132;                    // [128][72]
    float* mrow = Of + 128 * 72;
    float* lrow = mrow + 128;
    float* crow = lrow + 128;

    int tid = threadIdx.x, warp = tid >> 5;
    int h = blockIdx.y, n = blockIdx.z;
    int s0 = blockIdx.x * 128;

    const uint4* Qg = (const uint4*)(q2T + ((size_t)(n * 4 + h) * SV + s0) * 64);
    const uint4* Kg = (const uint4*)(kvT + ((size_t)(n * 8 + h) * 512) * 64);
    const uint4* Vg = (const uint4*)(kvT + ((size_t)(n * 8 + 4 + h) * 512) * 64);

    #pragma unroll
    for (int i = 0; i < 4; i++) {
        int idx = tid + i * 256;
        int r = idx >> 3, c = idx & 7;
        ((uint4*)(Qs + r * 72))[c] = Qg[r * 8 + c];
    }
    for (int i = tid; i < 128 * 72; i += 256) Of[i] = 0.f;
    if (tid < 128) { mrow[tid] = -1e30f; lrow[tid] = 0.f; }
    __syncthreads();

    for (int ch = 0; ch < 4; ch++) {
        #pragma unroll
        for (int i = 0; i < 4; i++) {
            int idx = tid + i * 256;
            int r = idx >> 3, c = idx & 7;
            ((uint4*)(Ks + r * 72))[c] = Kg[(ch * 128 + r) * 8 + c];
            ((uint4*)(Vs + r * 72))[c] = Vg[(ch * 128 + r) * 8 + c];
        }
        __syncthreads();

        {
            int wm = warp >> 2, wn = warp & 3;
            wmma::fragment<wmma::accumulator, 16, 16, 16, float> acc[4][2];
            #pragma unroll
            for (int i = 0; i < 4; i++)
                #pragma unroll
                for (int j = 0; j < 2; j++) wmma::fill_fragment(acc[i][j], 0.f);
            #pragma unroll
            for (int kd = 0; kd < 4; kd++) {
                wmma::fragment<wmma::matrix_a, 16, 16, 16, __nv_bfloat16, wmma::row_major> af[4];
                #pragma unroll
                for (int i = 0; i < 4; i++)
                    wmma::load_matrix_sync(af[i], Qs + (wm * 64 + i * 16) * 72 + kd * 16, 72);
                wmma::fragment<wmma::matrix_b, 16, 16, 16, __nv_bfloat16, wmma::col_major> bf[2];
                #pragma unroll
                for (int j = 0; j < 2; j++)
                    wmma::load_matrix_sync(bf[j], Ks + (wn * 32 + j * 16) * 72 + kd * 16, 72);
                #pragma unroll
                for (int i = 0; i < 4; i++)
                    #pragma unroll
                    for (int j = 0; j < 2; j++)
                        wmma::mma_sync(acc[i][j], af[i], bf[j], acc[i][j]);
            }
            #pragma unroll
            for (int i = 0; i < 4; i++)
                #pragma unroll
                for (int j = 0; j < 2; j++)
                    wmma::store_matrix_sync(Sf + (wm * 64 + i * 16) * 132 + wn * 32 + j * 16,
                                            acc[i][j], 132, wmma::mem_row_major);
        }
        __syncthreads();

        {
            int r = tid >> 1, half = tid & 1;
            const float* srow = Sf + r * 132 + half * 64;
            float cm = -1e30f;
            #pragma unroll
            for (int j = 0; j < 64; j++) cm = fmaxf(cm, srow[j]);
            cm = fmaxf(cm, __shfl_xor_sync(0xffffffffu, cm, 1));
            float mold = mrow[r];
            float mnew = fmaxf(mold, cm);
            float ls = 0.f;
            __nv_bfloat16* prow = Ps + r * 136 + half * 64;
            #pragma unroll
            for (int j = 0; j < 64; j++) {
                float p = __expf(srow[j] - mnew);
                ls += p;
                prow[j] = __float2bfloat16(p);
            }
            ls += __shfl_xor_sync(0xffffffffu, ls, 1);
            if (half == 0) {
                float corr = __expf(mold - mnew);
                lrow[r] = lrow[r] * corr + ls;
                mrow[r] = mnew;
                crow[r] = corr;
            }
        }
        __syncthreads();

        for (int i = tid; i < 128 * 64; i += 256) {
            int r = i >> 6, d = i & 63;
            Of[r * 72 + d] *= crow[r];
        }
        __syncthreads();

        {
            int pm = warp >> 1, pn = warp & 1;
            wmma::fragment<wmma::accumulator, 16, 16, 16, float> acc2[2][2];
            #pragma unroll
            for (int i = 0; i < 2; i++)
                #pragma unroll
                for (int j = 0; j < 2; j++)
                    wmma::load_matrix_sync(acc2[i][j],
                        Of + (pm * 32 + i * 16) * 72 + pn * 32 + j * 16, 72, wmma::mem_row_major);
            #pragma unroll
            for (int kk = 0; kk < 8; kk++) {
                wmma::fragment<wmma::matrix_a, 16, 16, 16, __nv_bfloat16, wmma::row_major> af[2];
                #pragma unroll
                for (int i = 0; i < 2; i++)
                    wmma::load_matrix_sync(af[i], Ps + (pm * 32 + i * 16) * 136 + kk * 16, 136);
                wmma::fragment<wmma::matrix_b, 16, 16, 16, __nv_bfloat16, wmma::row_major> bf[2];
                #pragma unroll
                for (int j = 0; j < 2; j++)
                    wmma::load_matrix_sync(bf[j], Vs + (kk * 16) * 72 + pn * 32 + j * 16, 72);
                #pragma unroll
                for (int i = 0; i < 2; i++)
                    #pragma unroll
                    for (int j = 0; j < 2; j++)
                        wmma::mma_sync(acc2[i][j], af[i], bf[j], acc2[i][j]);
            }
            #pragma unroll
            for (int i = 0; i < 2; i++)
                #pragma unroll
                for (int j = 0; j < 2; j++)
                    wmma::store_matrix_sync(Of + (pm * 32 + i * 16) * 72 + pn * 32 + j * 16,
                                            acc2[i][j], 72, wmma::mem_row_major);
        }
        __syncthreads();
    }

    #pragma unroll
    for (int i = 0; i < 32; i++) {
        int idx = tid + i * 256;
        int r = idx & 127, d = idx >> 7;
        float v = Of[r * 72 + d] / lrow[r];
        size_t gi = ((size_t)(n * 256 + h * 64 + d)) * SV + s0 + r;
        float t = v + attn[gi];
        __nv_bfloat16 hi = __float2bfloat16(t);
        ghi[gi] = hi;
        glo[gi] = __float2bfloat16(t - __bfloat162float(hi));
    }
}

// =========================================================================
// host launch
// =========================================================================
extern "C" void kernel_launch(void* const* d_in, const int* in_sizes, int n_in,
                              void* d_out, int out_size) {
    const float* x      = (const float*)d_in[0];
    const float* qkv_w  = (const float*)d_in[1];
    const float* qkv_b  = (const float*)d_in[2];
    const float* norm_w = (const float*)d_in[3];
    const float* norm_b = (const float*)d_in[4];
    const float* anorm_w= (const float*)d_in[5];
    const float* anorm_b= (const float*)d_in[6];
    const float* dnorm_w= (const float*)d_in[7];
    const float* dnorm_b= (const float*)d_in[8];
    const float* q_w    = (const float*)d_in[9];
    const float* q_b    = (const float*)d_in[10];
    const float* kv_w   = (const float*)d_in[11];
    const float* kv_b   = (const float*)d_in[12];
    const float* proj_w = (const float*)d_in[13];
    const float* proj_b = (const float*)d_in[14];
    float* out = (float*)d_out;

    float *attn, *pooled, *part, *stats, *aff;
    __nv_bfloat16 *xnB, *qkvB, *attnB, *ghi, *glo, *pooledB, *q2T, *kvT;
    __nv_bfloat16 *WqkvB, *WqB, *WkvB, *WprojB;
    cudaGetSymbolAddress((void**)&attn,    g_attn);
    cudaGetSymbolAddress((void**)&pooled,  g_pooled);
    cudaGetSymbolAddress((void**)&xnB,     g_xnB);
    cudaGetSymbolAddress((void**)&qkvB,    g_qkvB);
    cudaGetSymbolAddress((void**)&attnB,   g_attnB);
    cudaGetSymbolAddress((void**)&ghi,     g_ghi);
    cudaGetSymbolAddress((void**)&glo,     g_glo);
    cudaGetSymbolAddress((void**)&pooledB, g_pooledB);
    cudaGetSymbolAddress((void**)&q2T,     g_q2T);
    cudaGetSymbolAddress((void**)&kvT,     g_kvT);
    cudaGetSymbolAddress((void**)&WqkvB,   g_WqkvB);
    cudaGetSymbolAddress((void**)&WqB,     g_WqB);
    cudaGetSymbolAddress((void**)&WkvB,    g_WkvB);
    cudaGetSymbolAddress((void**)&WprojB,  g_WprojB);
    cudaGetSymbolAddress((void**)&part,    g_part);
    cudaGetSymbolAddress((void**)&stats,   g_stats);
    cudaGetSymbolAddress((void**)&aff,     g_aff);

    static bool attr_set = false;
    if (!attr_set) {
        cudaFuncSetAttribute(gattn_kernel, cudaFuncAttributeMaxDynamicSharedMemorySize, GA_SMEM);
        attr_set = true;
    }

    float* A0 = aff;        float* D0 = aff + 512;
    float* A1 = aff + 1024; float* D1 = aff + 1536;
    float* A2 = aff + 2048; float* D2 = aff + 2560;

    // weights -> bf16 (proj pre-split hi/lo/hi)
    convert_weights_kernel<<<2304, 256>>>(qkv_w, q_w, kv_w, proj_w,
                                          WqkvB, WqB, WkvB, WprojB);

    // GroupNorm(x) -> bf16 normed x
    reduce1_kernel<<<dim3(512, NB), 256>>>(x, 256L * SV, part);
    reduce2_kernel<<<NB, 256>>>(part, 512, stats);
    make_affine_kernel<<<NB, 256>>>(stats, norm_w, norm_b, A0, D0, 1.f / (256.f * 32768.f));
    convert_x_kernel<<<16384, 256>>>(x, A0, D0, xnB);

    // qkv conv -> window-gathered bf16 (q pre-scaled 1/16)
    wgemm2_kernel<2><<<dim3(12, 256, NB), 256, WG_SMEM>>>(
        WqkvB, xnB, xnB, qkv_b, nullptr, qkvB, 768, (int)SV, 256, SCALE_INV);

    // local windowed attention: attn = x + attn_out
    local_attn_w_kernel<<<dim3(512, NH, NB), 128>>>(qkvB, x, attn);

    // GroupNorm(x + attn) in place + bf16 copy
    reduce1_kernel<<<dim3(512, NB), 256>>>(attn, 256L * SV, part);
    reduce2_kernel<<<NB, 256>>>(part, 512, stats);
    make_affine_kernel<<<NB, 256>>>(stats, anorm_w, anorm_b, A1, D1, 1.f / (256.f * 32768.f));
    apply_norm2_kernel<<<16384, 256>>>(attn, A1, D1, attnB);

    // pool + ds GroupNorm -> bf16 pooled
    pool_kernel<<<1024, 256>>>(attn, pooled);
    reduce1_kernel<<<dim3(32, NB), 256>>>(pooled, 256L * 512, part);
    reduce2_kernel<<<NB, 256>>>(part, 32, stats);
    make_affine_kernel<<<NB, 256>>>(stats, dnorm_w, dnorm_b, A2, D2, 1.f / (256.f * 512.f));
    convert_pooled_kernel<<<256, 256>>>(pooled, A2, D2, pooledB);

    // kv conv -> kvT, q conv -> q2T (scaled 1/16)
    wgemm2_kernel<1><<<dim3(8, 4, NB), 256, WG_SMEM>>>(
        WkvB, pooledB, pooledB, kv_b, nullptr, kvT, 512, 512, 256, 1.f);
    wgemm2_kernel<1><<<dim3(4, 256, NB), 256, WG_SMEM>>>(
        WqB, attnB, attnB, q_b, nullptr, q2T, 256, (int)SV, 256, SCALE_INV);

    // global attention + residual -> bf16 hi/lo
    gattn_kernel<<<dim3(256, NH, NB), 256, GA_SMEM>>>(q2T, kvT, attn, ghi, glo);

    // final projection (3-term bf16 split) -> out
    wgemm2_kernel<0><<<dim3(4, 256, NB), 256, WG_SMEM>>>(
        WprojB, ghi, glo, proj_b, out, nullptr, 256, (int)SV, 768, 1.f);
}

// round 5
// speedup vs baseline: 2.8067x; 1.0701x over previous
#include <cuda_runtime.h>
#include <cuda_bf16.h>
#include <mma.h>
#include <math.h>
#include <stdint.h>

using namespace nvcuda;

#define NB 2
#define CH 256
#define SV 32768L
#define NH 4
#define HD 64
#define SCALE_INV 0.0625f
#define EPS 1e-6f

__device__ __forceinline__ unsigned pack2(float a, float b) {
    __nv_bfloat162 t = __floats2bfloat162_rn(a, b);
    return *reinterpret_cast<unsigned*>(&t);
}

// ---------------- scratch ----------------
__device__ __align__(16) float g_attn   [NB * 256L * SV];   // x + local attn (raw)
__device__ __align__(16) float g_praw   [NB * 256 * 512];   // window means of raw attn
__device__ __align__(16) float g_pnorm  [NB * 256 * 512];   // after anorm affine
__device__ __align__(16) __nv_bfloat16 g_xnB   [NB * 256L * SV];
__device__ __align__(16) __nv_bfloat16 g_qkvB  [NB * 768L * SV];
__device__ __align__(16) __nv_bfloat16 g_attnB [NB * 256L * SV];
__device__ __align__(16) __nv_bfloat16 g_ghi   [NB * 256L * SV];
__device__ __align__(16) __nv_bfloat16 g_glo   [NB * 256L * SV];
__device__ __align__(16) __nv_bfloat16 g_pooledB[NB * 256 * 512];
__device__ __align__(16) __nv_bfloat16 g_q2T   [NB * 4L * SV * 64];
__device__ __align__(16) __nv_bfloat16 g_kvT   [NB * 8L * 512 * 64];
__device__ __align__(16) __nv_bfloat16 g_WqkvB [768 * 256];
__device__ __align__(16) __nv_bfloat16 g_WqB   [256 * 256];
__device__ __align__(16) __nv_bfloat16 g_WkvB  [512 * 256];
__device__ __align__(16) __nv_bfloat16 g_WprojB[256 * 768];
__device__ float g_part [NB * 2048 * 2];
__device__ float g_stats[NB * 2];
__device__ float g_aff  [6 * NB * 256];

// ---------------- cp.async ----------------
__device__ __forceinline__ void cp16(void* dst, const void* src) {
    unsigned d = (unsigned)__cvta_generic_to_shared(dst);
    asm volatile("cp.async.cg.shared.global [%0], [%1], 16;\n" :: "r"(d), "l"(src));
}
#define CP_COMMIT asm volatile("cp.async.commit_group;\n" ::: "memory")
#define CP_WAIT1  asm volatile("cp.async.wait_group 1;\n" ::: "memory")
#define CP_WAIT0  asm volatile("cp.async.wait_group 0;\n" ::: "memory")

// =========================================================================
// reductions / affine / conversions
// =========================================================================
__global__ void reduce1_kernel(const float* __restrict__ buf, long per, float* __restrict__ part) {
    int n = blockIdx.y;
    const float* p = buf + (size_t)n * per;
    float s = 0.f, ss = 0.f;
    for (long i = (long)blockIdx.x * blockDim.x + threadIdx.x; i < per;
         i += (long)gridDim.x * blockDim.x) {
        float v = p[i];
        s += v; ss += v * v;
    }
    for (int o = 16; o; o >>= 1) {
        s  += __shfl_down_sync(0xffffffffu, s, o);
        ss += __shfl_down_sync(0xffffffffu, ss, o);
    }
    __shared__ float sh[64];
    int w = threadIdx.x >> 5;
    if ((threadIdx.x & 31) == 0) { sh[w] = s; sh[32 + w] = ss; }
    __syncthreads();
    if (threadIdx.x < 32) {
        int nw = blockDim.x >> 5;
        s  = (threadIdx.x < nw) ? sh[threadIdx.x]      : 0.f;
        ss = (threadIdx.x < nw) ? sh[32 + threadIdx.x] : 0.f;
        for (int o = 16; o; o >>= 1) {
            s  += __shfl_down_sync(0xffffffffu, s, o);
            ss += __shfl_down_sync(0xffffffffu, ss, o);
        }
        if (threadIdx.x == 0) {
            part[((size_t)n * gridDim.x + blockIdx.x) * 2 + 0] = s;
            part[((size_t)n * gridDim.x + blockIdx.x) * 2 + 1] = ss;
        }
    }
}

__global__ void reduce2_kernel(const float* __restrict__ part, int nb, float* __restrict__ stats) {
    int n = blockIdx.x;
    float s = 0.f, ss = 0.f;
    for (int i = threadIdx.x; i < nb; i += blockDim.x) {
        s  += part[((size_t)n * nb + i) * 2 + 0];
        ss += part[((size_t)n * nb + i) * 2 + 1];
    }
    for (int o = 16; o; o >>= 1) {
        s  += __shfl_down_sync(0xffffffffu, s, o);
        ss += __shfl_down_sync(0xffffffffu, ss, o);
    }
    __shared__ float sh[64];
    int w = threadIdx.x >> 5;
    if ((threadIdx.x & 31) == 0) { sh[w] = s; sh[32 + w] = ss; }
    __syncthreads();
    if (threadIdx.x < 32) {
        int nw = blockDim.x >> 5;
        s  = (threadIdx.x < nw) ? sh[threadIdx.x]      : 0.f;
        ss = (threadIdx.x < nw) ? sh[32 + threadIdx.x] : 0.f;
        for (int o = 16; o; o >>= 1) {
            s  += __shfl_down_sync(0xffffffffu, s, o);
            ss += __shfl_down_sync(0xffffffffu, ss, o);
        }
        if (threadIdx.x == 0) { stats[n * 2] = s; stats[n * 2 + 1] = ss; }
    }
}

__global__ void make_affine_kernel(const float* __restrict__ stats,
                                   const float* __restrict__ w, const float* __restrict__ b,
                                   float* __restrict__ a, float* __restrict__ d, float inv_cnt) {
    int c = threadIdx.x;
    int n = blockIdx.x;
    float mean = stats[n * 2] * inv_cnt;
    float var  = stats[n * 2 + 1] * inv_cnt - mean * mean;
    float rstd = rsqrtf(var + EPS);
    a[n * CH + c] = w[c] * rstd;
    d[n * CH + c] = b[c] - mean * rstd * w[c];
}

// fp32 [n][256][SV] -> bf16(a*x+d)
__global__ void convert_x_kernel(const float* __restrict__ x,
                                 const float* __restrict__ a, const float* __restrict__ d,
                                 __nv_bfloat16* __restrict__ out) {
    size_t i4 = (size_t)blockIdx.x * blockDim.x + threadIdx.x;
    int c = (int)((i4 >> 13) & 255);
    int n = (int)(i4 >> 21);
    float aa = a[n * CH + c], dd = d[n * CH + c];
    float4 v = reinterpret_cast<const float4*>(x)[i4];
    uint2 r;
    r.x = pack2(fmaf(aa, v.x, dd), fmaf(aa, v.y, dd));
    r.y = pack2(fmaf(aa, v.z, dd), fmaf(aa, v.w, dd));
    reinterpret_cast<uint2*>(out)[i4] = r;
}

// pooled_raw -> pooled_norm (anorm affine, fp32)
__global__ void apply_pool_affine_kernel(const float* __restrict__ praw,
                                         const float* __restrict__ a, const float* __restrict__ d,
                                         float* __restrict__ pnorm) {
    size_t i4 = (size_t)blockIdx.x * blockDim.x + threadIdx.x;  // 65536 float4
    int c = (int)((i4 >> 7) & 255);
    int n = (int)(i4 >> 15);
    float aa = a[n * CH + c], dd = d[n * CH + c];
    float4 v = reinterpret_cast<const float4*>(praw)[i4];
    v.x = fmaf(aa, v.x, dd); v.y = fmaf(aa, v.y, dd);
    v.z = fmaf(aa, v.z, dd); v.w = fmaf(aa, v.w, dd);
    reinterpret_cast<float4*>(pnorm)[i4] = v;
}

// pooled_norm -> bf16(a2*pn+d2)
__global__ void convert_pooled_kernel(const float* __restrict__ pooled,
                                      const float* __restrict__ a, const float* __restrict__ d,
                                      __nv_bfloat16* __restrict__ out) {
    size_t i4 = (size_t)blockIdx.x * blockDim.x + threadIdx.x;
    int c = (int)((i4 >> 7) & 255);
    int n = (int)(i4 >> 15);
    float aa = a[n * CH + c], dd = d[n * CH + c];
    float4 v = reinterpret_cast<const float4*>(pooled)[i4];
    uint2 r;
    r.x = pack2(fmaf(aa, v.x, dd), fmaf(aa, v.y, dd));
    r.y = pack2(fmaf(aa, v.z, dd), fmaf(aa, v.w, dd));
    reinterpret_cast<uint2*>(out)[i4] = r;
}

__global__ void convert_weights_kernel(
    const float* __restrict__ qkv_w, const float* __restrict__ q_w,
    const float* __restrict__ kv_w, const float* __restrict__ proj_w,
    __nv_bfloat16* __restrict__ Wqkv, __nv_bfloat16* __restrict__ Wq,
    __nv_bfloat16* __restrict__ Wkv, __nv_bfloat16* __restrict__ Wproj) {
    int idx = blockIdx.x * blockDim.x + threadIdx.x;
    const int T1 = 768 * 256, T2 = T1 + 256 * 256, T3 = T2 + 512 * 256, T4 = T3 + 256 * 768;
    if (idx < T1) {
        Wqkv[idx] = __float2bfloat16(qkv_w[idx]);
    } else if (idx < T2) {
        int j = idx - T1; Wq[j] = __float2bfloat16(q_w[j]);
    } else if (idx < T3) {
        int j = idx - T2; Wkv[j] = __float2bfloat16(kv_w[j]);
    } else if (idx < T4) {
        int j = idx - T3;
        int m = j / 768, k = j % 768;
        float v = proj_w[m * 256 + (k & 255)];
        __nv_bfloat16 hi = __float2bfloat16(v);
        if (k >= 256 && k < 512) hi = __float2bfloat16(v - __bfloat162float(hi));
        Wproj[j] = hi;
    }
}

// =========================================================================
// wgemm3: BM=128, BN=128, BK=32, 3-stage cp.async, 256 threads.
// warp tile 64x32 (2x4 warp grid). A bf16 [M][KT], B bf16 [z][256][S].
// MODE 0: fp32 out + bias  MODE 1: bf16 head-T layout  MODE 2: bf16 window
// =========================================================================
#define WG_SMEM 69632

template<int MODE>
__global__ void __launch_bounds__(256) wgemm3_kernel(
    const __nv_bfloat16* __restrict__ A,
    const __nv_bfloat16* __restrict__ B0, const __nv_bfloat16* __restrict__ B1,
    const float* __restrict__ bias,
    float* __restrict__ outF, __nv_bfloat16* __restrict__ outB,
    int M, int S, int KT, float qScale) {
    extern __shared__ __align__(16) char dsm[];
    __nv_bfloat16* As = (__nv_bfloat16*)dsm;             // 3 x [128*40]
    __nv_bfloat16* Bs = (__nv_bfloat16*)(dsm + 30720);   // 3 x [32*136]
    float* Cs = (float*)dsm;                             // [128][132] after loop

    int tid = threadIdx.x, warp = tid >> 5;
    int wm = warp >> 2, wn = warp & 3;                   // 2 x 4
    int m0 = blockIdx.x * 128;
    int s0 = blockIdx.y * 128;
    int z  = blockIdx.z;

    const __nv_bfloat16* Bb0 = B0 + (size_t)z * 256 * S;
    const __nv_bfloat16* Bb1 = B1 + (size_t)z * 256 * S;

    wmma::fragment<wmma::accumulator, 16, 16, 16, float> acc[4][2];
    #pragma unroll
    for (int i = 0; i < 4; i++)
        #pragma unroll
        for (int j = 0; j < 2; j++) wmma::fill_fragment(acc[i][j], 0.f);

    const int NIT = KT >> 5;

    auto prefetch = [&](int it, int buf) {
        int ktL = it * 32;
        // A: 128x32 -> 512 x 16B
        #pragma unroll
        for (int i = 0; i < 2; i++) {
            int c = tid + i * 256;
            int r = c >> 2, q = (c & 3) * 8;
            cp16(As + buf * 5120 + r * 40 + q,
                 A + (size_t)(m0 + r) * KT + ktL + q);
        }
        // B: 32x128 -> 512 x 16B
        const __nv_bfloat16* Bp = (ktL < 512) ? Bb0 : Bb1;
        int krow = ktL & 255;
        #pragma unroll
        for (int i = 0; i < 2; i++) {
            int c = tid + i * 256;
            int r = c >> 4, q = (c & 15) * 8;
            cp16(Bs + buf * 4352 + r * 136 + q,
                 Bp + (size_t)(krow + r) * S + s0 + q);
        }
    };

    prefetch(0, 0); CP_COMMIT;
    prefetch(1, 1); CP_COMMIT;

    int buf = 0;
    for (int it = 0; it < NIT; it++) {
        if (it + 1 < NIT) CP_WAIT1; else CP_WAIT0;
        __syncthreads();
        #pragma unroll
        for (int ks = 0; ks < 2; ks++) {
            wmma::fragment<wmma::matrix_a, 16, 16, 16, __nv_bfloat16, wmma::row_major> af[4];
            #pragma unroll
            for (int i = 0; i < 4; i++)
                wmma::load_matrix_sync(af[i], As + buf * 5120 + (wm * 64 + i * 16) * 40 + ks * 16, 40);
            wmma::fragment<wmma::matrix_b, 16, 16, 16, __nv_bfloat16, wmma::row_major> bf[2];
            #pragma unroll
            for (int j = 0; j < 2; j++)
                wmma::load_matrix_sync(bf[j], Bs + buf * 4352 + (ks * 16) * 136 + wn * 32 + j * 16, 136);
            #pragma unroll
            for (int i = 0; i < 4; i++)
                #pragma unroll
                for (int j = 0; j < 2; j++)
                    wmma::mma_sync(acc[i][j], af[i], bf[j], acc[i][j]);
        }
        if (it + 2 < NIT) {
            prefetch(it + 2, (buf + 2) % 3);
            CP_COMMIT;
        }
        buf = (buf + 1) % 3;
    }

    __syncthreads();   // pipeline buffers -> Cs reuse
    #pragma unroll
    for (int i = 0; i < 4; i++)
        #pragma unroll
        for (int j = 0; j < 2; j++)
            wmma::store_matrix_sync(Cs + (wm * 64 + i * 16) * 132 + wn * 32 + j * 16,
                                    acc[i][j], 132, wmma::mem_row_major);
    __syncthreads();

    if (MODE == 0) {
        float* Ob = outF + ((size_t)z * M + m0) * S;
        #pragma unroll
        for (int it = 0; it < 16; it++) {
            int idx = tid + it * 256;
            int r = idx >> 5, c4 = idx & 31;
            float bv = bias[m0 + r];
            float4 v = *reinterpret_cast<const float4*>(&Cs[r * 132 + c4 * 4]);
            v.x += bv; v.y += bv; v.z += bv; v.w += bv;
            *reinterpret_cast<float4*>(&Ob[(size_t)r * S + s0 + c4 * 4]) = v;
        }
    } else {
        #pragma unroll
        for (int it = 0; it < 8; it++) {
            int idx = tid + it * 256;
            int sl = idx & 127, dg = idx >> 7;     // dg: 0..15, 8 dims each
            int gmb = m0 + dg * 8;
            float sc;
            size_t off;
            __nv_bfloat16* base;
            if (MODE == 1) {
                int hb = gmb >> 6, db = gmb & 63;
                sc = qScale;
                base = outB + ((size_t)(z * (M >> 6) + hb) * S + s0 + sl) * 64;
                off = db;
            } else {
                int sel = gmb >> 8, head = (gmb >> 6) & 3, db = gmb & 63;
                sc = (sel == 0) ? qScale : 1.f;
                int s = s0 + sl;
                int d5 = s & 31, w5 = (s >> 5) & 31, h5 = s >> 10;
                int window = ((h5 >> 2) * 8 + (w5 >> 2)) * 8 + (d5 >> 2);
                int token  = (((h5 & 3) * 4 + (w5 & 3)) * 4 + (d5 & 3));
                base = outB + (((size_t)(z * 3 + sel) * 4 + head) * 512) * 4096;
                off = (size_t)window * 4096 + token * 64 + db;
            }
            float f[8];
            #pragma unroll
            for (int e = 0; e < 8; e++)
                f[e] = (Cs[(dg * 8 + e) * 132 + sl] + bias[gmb + e]) * sc;
            uint4 u;
            u.x = pack2(f[0], f[1]);
            u.y = pack2(f[2], f[3]);
            u.z = pack2(f[4], f[5]);
            u.w = pack2(f[6], f[7]);
            *reinterpret_cast<uint4*>(base + off) = u;
        }
    }
}

// =========================================================================
// Local windowed attention (wmma) + fused pool sums + groupnorm partials
// =========================================================================
__global__ void __launch_bounds__(128) local_attn_w_kernel(
    const __nv_bfloat16* __restrict__ qkvB, const float* __restrict__ x,
    float* __restrict__ attn, float* __restrict__ praw, float* __restrict__ part) {
    __shared__ __align__(16) __nv_bfloat16 QP[64 * 72];
    __shared__ __align__(16) __nv_bfloat16 Ks[64 * 72];
    __shared__ __align__(16) __nv_bfloat16 Vs[64 * 72];
    __shared__ __align__(16) float Sf[64 * 68];
    __shared__ float linv[64];
    __shared__ float rs[4], rss[4];

    int w = blockIdx.x, head = blockIdx.y, n = blockIdx.z;
    int tid = threadIdx.x, warp = tid >> 5;

    size_t base = (((size_t)(n * 3) * 4 + head) * 512 + w) * 4096;
    size_t step = (size_t)4 * 512 * 4096;
    const uint4* Qg = (const uint4*)(qkvB + base);
    const uint4* Kg = (const uint4*)(qkvB + base + step);
    const uint4* Vg = (const uint4*)(qkvB + base + 2 * step);

    #pragma unroll
    for (int i = 0; i < 4; i++) {
        int c = tid + i * 128;
        int r = c >> 3, q = c & 7;
        ((uint4*)(QP + r * 72))[q] = Qg[c];
        ((uint4*)(Ks + r * 72))[q] = Kg[c];
        ((uint4*)(Vs + r * 72))[q] = Vg[c];
    }
    __syncthreads();

    // S = Q @ K^T
    {
        int m = warp * 16;
        wmma::fragment<wmma::accumulator, 16, 16, 16, float> acc[4];
        #pragma unroll
        for (int j = 0; j < 4; j++) wmma::fill_fragment(acc[j], 0.f);
        #pragma unroll
        for (int kd = 0; kd < 4; kd++) {
            wmma::fragment<wmma::matrix_a, 16, 16, 16, __nv_bfloat16, wmma::row_major> af;
            wmma::load_matrix_sync(af, QP + m * 72 + kd * 16, 72);
            #pragma unroll
            for (int j = 0; j < 4; j++) {
                wmma::fragment<wmma::matrix_b, 16, 16, 16, __nv_bfloat16, wmma::col_major> bf;
                wmma::load_matrix_sync(bf, Ks + (j * 16) * 72 + kd * 16, 72);
                wmma::mma_sync(acc[j], af, bf, acc[j]);
            }
        }
        #pragma unroll
        for (int j = 0; j < 4; j++)
            wmma::store_matrix_sync(Sf + m * 68 + j * 16, acc[j], 68, wmma::mem_row_major);
    }
    __syncthreads();

    // softmax
    {
        int r = tid >> 1, hf = tid & 1;
        const float* srow = Sf + r * 68 + hf * 32;
        float mx = -1e30f;
        #pragma unroll
        for (int j = 0; j < 32; j++) mx = fmaxf(mx, srow[j]);
        mx = fmaxf(mx, __shfl_xor_sync(0xffffffffu, mx, 1));
        float ls = 0.f;
        __nv_bfloat16* prow = QP + r * 72 + hf * 32;
        #pragma unroll
        for (int j = 0; j < 32; j++) {
            float p = __expf(srow[j] - mx);
            ls += p;
            prow[j] = __float2bfloat16(p);
        }
        ls += __shfl_xor_sync(0xffffffffu, ls, 1);
        if (hf == 0) linv[r] = 1.f / ls;
    }
    __syncthreads();

    // O = P @ V -> Sf
    {
        int m = warp * 16;
        wmma::fragment<wmma::accumulator, 16, 16, 16, float> acc[4];
        #pragma unroll
        for (int j = 0; j < 4; j++) wmma::fill_fragment(acc[j], 0.f);
        #pragma unroll
        for (int kk = 0; kk < 4; kk++) {
            wmma::fragment<wmma::matrix_a, 16, 16, 16, __nv_bfloat16, wmma::row_major> af;
            wmma::load_matrix_sync(af, QP + m * 72 + kk * 16, 72);
            #pragma unroll
            for (int j = 0; j < 4; j++) {
                wmma::fragment<wmma::matrix_b, 16, 16, 16, __nv_bfloat16, wmma::row_major> bf;
                wmma::load_matrix_sync(bf, Vs + (kk * 16) * 72 + j * 16, 72);
                wmma::mma_sync(acc[j], af, bf, acc[j]);
            }
        }
        #pragma unroll
        for (int j = 0; j < 4; j++)
            wmma::store_matrix_sync(Sf + m * 68 + j * 16, acc[j], 68, wmma::mem_row_major);
    }
    __syncthreads();

    // epilogue: attn = x + O/l, plus pool sums and groupnorm partials
    int wh = w >> 6, ww = (w >> 3) & 7, wd = w & 7;
    int base_s = wh * 4096 + ww * 128 + wd * 4;
    int chb = n * 256 + head * 64;
    float s_acc = 0.f, ss_acc = 0.f;
    #pragma unroll
    for (int it = 0; it < 8; it++) {
        int idx = tid + it * 128;
        int d = idx >> 4, tg = idx & 15;
        int i_ = tg >> 2, j_ = tg & 3;
        int s = base_s + i_ * 1024 + j_ * 32;
        int t0 = tg * 4;
        size_t g = ((size_t)(chb + d)) * SV + s;
        float4 xv = *reinterpret_cast<const float4*>(x + g);
        float4 ov;
        ov.x = fmaf(Sf[(t0 + 0) * 68 + d], linv[t0 + 0], xv.x);
        ov.y = fmaf(Sf[(t0 + 1) * 68 + d], linv[t0 + 1], xv.y);
        ov.z = fmaf(Sf[(t0 + 2) * 68 + d], linv[t0 + 2], xv.z);
        ov.w = fmaf(Sf[(t0 + 3) * 68 + d], linv[t0 + 3], xv.w);
        *reinterpret_cast<float4*>(attn + g) = ov;
        float ps = ov.x + ov.y + ov.z + ov.w;
        s_acc  += ps;
        ss_acc += ov.x*ov.x + ov.y*ov.y + ov.z*ov.z + ov.w*ov.w;
        // pool: reduce ps over the 16 lanes sharing this dim
        #pragma unroll
        for (int o = 8; o; o >>= 1) ps += __shfl_down_sync(0xffffffffu, ps, o);
        if ((tid & 15) == 0)
            praw[((size_t)(chb + d)) * 512 + w] = ps * (1.f / 64.f);
    }
    // block stats -> part
    #pragma unroll
    for (int o = 16; o; o >>= 1) {
        s_acc  += __shfl_down_sync(0xffffffffu, s_acc, o);
        ss_acc += __shfl_down_sync(0xffffffffu, ss_acc, o);
    }
    if ((tid & 31) == 0) { rs[warp] = s_acc; rss[warp] = ss_acc; }
    __syncthreads();
    if (tid == 0) {
        size_t pi = (size_t)n * 2048 + head * 512 + w;
        part[pi * 2 + 0] = rs[0] + rs[1] + rs[2] + rs[3];
        part[pi * 2 + 1] = rss[0] + rss[1] + rss[2] + rss[3];
    }
}

// =========================================================================
// Global attention (wmma, online softmax); residual uses raw attn + affine
// =========================================================================
#define GA_SMEM 196096

__global__ void __launch_bounds__(256) gattn_kernel(
    const __nv_bfloat16* __restrict__ q2T, const __nv_bfloat16* __restrict__ kvT,
    const float* __restrict__ attn,
    const float* __restrict__ A1, const float* __restrict__ D1,
    __nv_bfloat16* __restrict__ ghi, __nv_bfloat16* __restrict__ glo) {
    extern __shared__ __align__(16) char sm[];
    __nv_bfloat16* Qs = (__nv_bfloat16*)sm;
    __nv_bfloat16* Ks = Qs + 128 * 72;
    __nv_bfloat16* Vs = Ks + 128 * 72;
    __nv_bfloat16* Ps = Vs + 128 * 72;
    float* Sf   = (float*)(Ps + 128 * 136);
    float* Of   = Sf + 128 * 132;
    float* mrow = Of + 128 * 72;
    float* lrow = mrow + 128;
    float* crow = lrow + 128;

    int tid = threadIdx.x, warp = tid >> 5;
    int h = blockIdx.y, n = blockIdx.z;
    int s0 = blockIdx.x * 128;

    const uint4* Qg = (const uint4*)(q2T + ((size_t)(n * 4 + h) * SV + s0) * 64);
    const uint4* Kg = (const uint4*)(kvT + ((size_t)(n * 8 + h) * 512) * 64);
    const uint4* Vg = (const uint4*)(kvT + ((size_t)(n * 8 + 4 + h) * 512) * 64);

    #pragma unroll
    for (int i = 0; i < 4; i++) {
        int idx = tid + i * 256;
        int r = idx >> 3, c = idx & 7;
        ((uint4*)(Qs + r * 72))[c] = Qg[r * 8 + c];
    }
    for (int i = tid; i < 128 * 72; i += 256) Of[i] = 0.f;
    if (tid < 128) { mrow[tid] = -1e30f; lrow[tid] = 0.f; }
    __syncthreads();

    for (int ch = 0; ch < 4; ch++) {
        #pragma unroll
        for (int i = 0; i < 4; i++) {
            int idx = tid + i * 256;
            int r = idx >> 3, c = idx & 7;
            ((uint4*)(Ks + r * 72))[c] = Kg[(ch * 128 + r) * 8 + c];
            ((uint4*)(Vs + r * 72))[c] = Vg[(ch * 128 + r) * 8 + c];
        }
        __syncthreads();

        {
            int wm = warp >> 2, wn = warp & 3;
            wmma::fragment<wmma::accumulator, 16, 16, 16, float> acc[4][2];
            #pragma unroll
            for (int i = 0; i < 4; i++)
                #pragma unroll
                for (int j = 0; j < 2; j++) wmma::fill_fragment(acc[i][j], 0.f);
            #pragma unroll
            for (int kd = 0; kd < 4; kd++) {
                wmma::fragment<wmma::matrix_a, 16, 16, 16, __nv_bfloat16, wmma::row_major> af[4];
                #pragma unroll
                for (int i = 0; i < 4; i++)
                    wmma::load_matrix_sync(af[i], Qs + (wm * 64 + i * 16) * 72 + kd * 16, 72);
                wmma::fragment<wmma::matrix_b, 16, 16, 16, __nv_bfloat16, wmma::col_major> bf[2];
                #pragma unroll
                for (int j = 0; j < 2; j++)
                    wmma::load_matrix_sync(bf[j], Ks + (wn * 32 + j * 16) * 72 + kd * 16, 72);
                #pragma unroll
                for (int i = 0; i < 4; i++)
                    #pragma unroll
                    for (int j = 0; j < 2; j++)
                        wmma::mma_sync(acc[i][j], af[i], bf[j], acc[i][j]);
            }
            #pragma unroll
            for (int i = 0; i < 4; i++)
                #pragma unroll
                for (int j = 0; j < 2; j++)
                    wmma::store_matrix_sync(Sf + (wm * 64 + i * 16) * 132 + wn * 32 + j * 16,
                                            acc[i][j], 132, wmma::mem_row_major);
        }
        __syncthreads();

        {
            int r = tid >> 1, half = tid & 1;
            const float* srow = Sf + r * 132 + half * 64;
            float cm = -1e30f;
            #pragma unroll
            for (int j = 0; j < 64; j++) cm = fmaxf(cm, srow[j]);
            cm = fmaxf(cm, __shfl_xor_sync(0xffffffffu, cm, 1));
            float mold = mrow[r];
            float mnew = fmaxf(mold, cm);
            float ls = 0.f;
            __nv_bfloat16* prow = Ps + r * 136 + half * 64;
            #pragma unroll
            for (int j = 0; j < 64; j++) {
                float p = __expf(srow[j] - mnew);
                ls += p;
                prow[j] = __float2bfloat16(p);
            }
            ls += __shfl_xor_sync(0xffffffffu, ls, 1);
            if (half == 0) {
                float corr = __expf(mold - mnew);
                lrow[r] = lrow[r] * corr + ls;
                mrow[r] = mnew;
                crow[r] = corr;
            }
        }
        __syncthreads();

        for (int i = tid; i < 128 * 64; i += 256) {
            int r = i >> 6, d = i & 63;
            Of[r * 72 + d] *= crow[r];
        }
        __syncthreads();

        {
            int pm = warp >> 1, pn = warp & 1;
            wmma::fragment<wmma::accumulator, 16, 16, 16, float> acc2[2][2];
            #pragma unroll
            for (int i = 0; i < 2; i++)
                #pragma unroll
                for (int j = 0; j < 2; j++)
                    wmma::load_matrix_sync(acc2[i][j],
                        Of + (pm * 32 + i * 16) * 72 + pn * 32 + j * 16, 72, wmma::mem_row_major);
            #pragma unroll
            for (int kk = 0; kk < 8; kk++) {
                wmma::fragment<wmma::matrix_a, 16, 16, 16, __nv_bfloat16, wmma::row_major> af[2];
                #pragma unroll
                for (int i = 0; i < 2; i++)
                    wmma::load_matrix_sync(af[i], Ps + (pm * 32 + i * 16) * 136 + kk * 16, 136);
                wmma::fragment<wmma::matrix_b, 16, 16, 16, __nv_bfloat16, wmma::row_major> bf[2];
                #pragma unroll
                for (int j = 0; j < 2; j++)
                    wmma::load_matrix_sync(bf[j], Vs + (kk * 16) * 72 + pn * 32 + j * 16, 72);
                #pragma unroll
                for (int i = 0; i < 2; i++)
                    #pragma unroll
                    for (int j = 0; j < 2; j++)
                        wmma::mma_sync(acc2[i][j], af[i], bf[j], acc2[i][j]);
            }
            #pragma unroll
            for (int i = 0; i < 2; i++)
                #pragma unroll
                for (int j = 0; j < 2; j++)
                    wmma::store_matrix_sync(Of + (pm * 32 + i * 16) * 72 + pn * 32 + j * 16,
                                            acc2[i][j], 72, wmma::mem_row_major);
        }
        __syncthreads();
    }

    #pragma unroll
    for (int i = 0; i < 32; i++) {
        int idx = tid + i * 256;
        int r = idx & 127, d = idx >> 7;
        int cch = n * 256 + h * 64 + d;
        float v = Of[r * 72 + d] / lrow[r];
        size_t gi = ((size_t)cch) * SV + s0 + r;
        float t = v + fmaf(A1[cch], attn[gi], D1[cch]);
        __nv_bfloat16 hi = __float2bfloat16(t);
        ghi[gi] = hi;
        glo[gi] = __float2bfloat16(t - __bfloat162float(hi));
    }
}

// =========================================================================
// host launch
// =========================================================================
extern "C" void kernel_launch(void* const* d_in, const int* in_sizes, int n_in,
                              void* d_out, int out_size) {
    const float* x      = (const float*)d_in[0];
    const float* qkv_w  = (const float*)d_in[1];
    const float* qkv_b  = (const float*)d_in[2];
    const float* norm_w = (const float*)d_in[3];
    const float* norm_b = (const float*)d_in[4];
    const float* anorm_w= (const float*)d_in[5];
    const float* anorm_b= (const float*)d_in[6];
    const float* dnorm_w= (const float*)d_in[7];
    const float* dnorm_b= (const float*)d_in[8];
    const float* q_w    = (const float*)d_in[9];
    const float* q_b    = (const float*)d_in[10];
    const float* kv_w   = (const float*)d_in[11];
    const float* kv_b   = (const float*)d_in[12];
    const float* proj_w = (const float*)d_in[13];
    const float* proj_b = (const float*)d_in[14];
    float* out = (float*)d_out;

    float *attn, *praw, *pnorm, *part, *stats, *aff;
    __nv_bfloat16 *xnB, *qkvB, *attnB, *ghi, *glo, *pooledB, *q2T, *kvT;
    __nv_bfloat16 *WqkvB, *WqB, *WkvB, *WprojB;
    cudaGetSymbolAddress((void**)&attn,    g_attn);
    cudaGetSymbolAddress((void**)&praw,    g_praw);
    cudaGetSymbolAddress((void**)&pnorm,   g_pnorm);
    cudaGetSymbolAddress((void**)&xnB,     g_xnB);
    cudaGetSymbolAddress((void**)&qkvB,    g_qkvB);
    cudaGetSymbolAddress((void**)&attnB,   g_attnB);
    cudaGetSymbolAddress((void**)&ghi,     g_ghi);
    cudaGetSymbolAddress((void**)&glo,     g_glo);
    cudaGetSymbolAddress((void**)&pooledB, g_pooledB);
    cudaGetSymbolAddress((void**)&q2T,     g_q2T);
    cudaGetSymbolAddress((void**)&kvT,     g_kvT);
    cudaGetSymbolAddress((void**)&WqkvB,   g_WqkvB);
    cudaGetSymbolAddress((void**)&WqB,     g_WqB);
    cudaGetSymbolAddress((void**)&WkvB,    g_WkvB);
    cudaGetSymbolAddress((void**)&WprojB,  g_WprojB);
    cudaGetSymbolAddress((void**)&part,    g_part);
    cudaGetSymbolAddress((void**)&stats,   g_stats);
    cudaGetSymbolAddress((void**)&aff,     g_aff);

    static bool attr_set = false;
    if (!attr_set) {
        cudaFuncSetAttribute(gattn_kernel, cudaFuncAttributeMaxDynamicSharedMemorySize, GA_SMEM);
        cudaFuncSetAttribute(wgemm3_kernel<0>, cudaFuncAttributeMaxDynamicSharedMemorySize, WG_SMEM);
        cudaFuncSetAttribute(wgemm3_kernel<1>, cudaFuncAttributeMaxDynamicSharedMemorySize, WG_SMEM);
        cudaFuncSetAttribute(wgemm3_kernel<2>, cudaFuncAttributeMaxDynamicSharedMemorySize, WG_SMEM);
        attr_set = true;
    }

    float* A0 = aff;        float* D0 = aff + 512;
    float* A1 = aff + 1024; float* D1 = aff + 1536;
    float* A2 = aff + 2048; float* D2 = aff + 2560;

    convert_weights_kernel<<<2304, 256>>>(qkv_w, q_w, kv_w, proj_w,
                                          WqkvB, WqB, WkvB, WprojB);

    // GroupNorm(x) -> bf16 normed x
    reduce1_kernel<<<dim3(512, NB), 256>>>(x, 256L * SV, part);
    reduce2_kernel<<<NB, 256>>>(part, 512, stats);
    make_affine_kernel<<<NB, 256>>>(stats, norm_w, norm_b, A0, D0, 1.f / (256.f * 32768.f));
    convert_x_kernel<<<16384, 256>>>(x, A0, D0, xnB);

    // qkv conv -> window-gathered bf16 (q pre-scaled 1/16)
    wgemm3_kernel<2><<<dim3(6, 256, NB), 256, WG_SMEM>>>(
        WqkvB, xnB, xnB, qkv_b, nullptr, qkvB, 768, (int)SV, 256, SCALE_INV);

    // local attention: attn(raw) + pooled sums + groupnorm partials
    local_attn_w_kernel<<<dim3(512, NH, NB), 128>>>(qkvB, x, attn, praw, part);

    // anorm affine from fused partials
    reduce2_kernel<<<NB, 256>>>(part, 2048, stats);
    make_affine_kernel<<<NB, 256>>>(stats, anorm_w, anorm_b, A1, D1, 1.f / (256.f * 32768.f));

    // attnB = bf16(anorm(attn))
    convert_x_kernel<<<16384, 256>>>(attn, A1, D1, attnB);

    // pooled: affine -> ds-norm stats -> bf16
    apply_pool_affine_kernel<<<256, 256>>>(praw, A1, D1, pnorm);
    reduce1_kernel<<<dim3(32, NB), 256>>>(pnorm, 256L * 512, part);
    reduce2_kernel<<<NB, 256>>>(part, 32, stats);
    make_affine_kernel<<<NB, 256>>>(stats, dnorm_w, dnorm_b, A2, D2, 1.f / (256.f * 512.f));
    convert_pooled_kernel<<<256, 256>>>(pnorm, A2, D2, pooledB);

    // kv conv -> kvT, q conv -> q2T (scaled 1/16)
    wgemm3_kernel<1><<<dim3(4, 4, NB), 256, WG_SMEM>>>(
        WkvB, pooledB, pooledB, kv_b, nullptr, kvT, 512, 512, 256, 1.f);
    wgemm3_kernel<1><<<dim3(2, 256, NB), 256, WG_SMEM>>>(
        WqB, attnB, attnB, q_b, nullptr, q2T, 256, (int)SV, 256, SCALE_INV);

    // global attention + affine residual -> bf16 hi/lo
    gattn_kernel<<<dim3(256, NH, NB), 256, GA_SMEM>>>(q2T, kvT, attn, A1, D1, ghi, glo);

    // final projection (3-term bf16 split) -> out
    wgemm3_kernel<0><<<dim3(2, 256, NB), 256, WG_SMEM>>>(
        WprojB, ghi, glo, proj_b, out, nullptr, 256, (int)SV, 768, 1.f);
}

// round 6
// speedup vs baseline: 3.7384x; 1.3320x over previous
#include <cuda_runtime.h>
#include <cuda_bf16.h>
#include <mma.h>
#include <math.h>
#include <stdint.h>

using namespace nvcuda;

#define NB 2
#define CH 256
#define SV 32768L
#define NH 4
#define HD 64
#define SCALE_INV 0.0625f
#define EPS 1e-6f

__device__ __forceinline__ unsigned pack2(float a, float b) {
    __nv_bfloat162 t = __floats2bfloat162_rn(a, b);
    return *reinterpret_cast<unsigned*>(&t);
}

// ---------------- scratch ----------------
__device__ __align__(16) float g_attn   [NB * 256L * SV];   // x + local attn (raw)
__device__ __align__(16) float g_praw   [NB * 256 * 512];
__device__ __align__(16) float g_pnorm  [NB * 256 * 512];
__device__ __align__(16) __nv_bfloat16 g_xnB   [NB * 256L * SV];
__device__ __align__(16) __nv_bfloat16 g_qkvB  [NB * 768L * SV];
__device__ __align__(16) __nv_bfloat16 g_attnB [NB * 256L * SV];
__device__ __align__(16) __nv_bfloat16 g_ghi   [NB * 256L * SV];
__device__ __align__(16) __nv_bfloat16 g_glo   [NB * 256L * SV];
__device__ __align__(16) __nv_bfloat16 g_pooledB[NB * 256 * 512];
__device__ __align__(16) __nv_bfloat16 g_q2T   [NB * 4L * SV * 64];
__device__ __align__(16) __nv_bfloat16 g_kvT   [NB * 8L * 512 * 64];
__device__ __align__(16) __nv_bfloat16 g_WqkvB [768 * 256];
__device__ __align__(16) __nv_bfloat16 g_WqB   [256 * 256];
__device__ __align__(16) __nv_bfloat16 g_WkvB  [512 * 256];
__device__ __align__(16) __nv_bfloat16 g_WprojB[256 * 768];
__device__ float g_part [NB * 2048 * 2];
__device__ float g_stats[NB * 2];
__device__ float g_aff  [6 * NB * 256];

// ---------------- cp.async ----------------
__device__ __forceinline__ void cp16(void* dst, const void* src) {
    unsigned d = (unsigned)__cvta_generic_to_shared(dst);
    asm volatile("cp.async.cg.shared.global [%0], [%1], 16;\n" :: "r"(d), "l"(src));
}
#define CP_COMMIT asm volatile("cp.async.commit_group;\n" ::: "memory")
#define CP_WAIT1  asm volatile("cp.async.wait_group 1;\n" ::: "memory")
#define CP_WAIT0  asm volatile("cp.async.wait_group 0;\n" ::: "memory")

// =========================================================================
// reductions / affine / conversions
// =========================================================================
__global__ void reduce1_kernel(const float* __restrict__ buf, long per, float* __restrict__ part) {
    int n = blockIdx.y;
    const float* p = buf + (size_t)n * per;
    float s = 0.f, ss = 0.f;
    for (long i = (long)blockIdx.x * blockDim.x + threadIdx.x; i < per;
         i += (long)gridDim.x * blockDim.x) {
        float v = p[i];
        s += v; ss += v * v;
    }
    for (int o = 16; o; o >>= 1) {
        s  += __shfl_down_sync(0xffffffffu, s, o);
        ss += __shfl_down_sync(0xffffffffu, ss, o);
    }
    __shared__ float sh[64];
    int w = threadIdx.x >> 5;
    if ((threadIdx.x & 31) == 0) { sh[w] = s; sh[32 + w] = ss; }
    __syncthreads();
    if (threadIdx.x < 32) {
        int nw = blockDim.x >> 5;
        s  = (threadIdx.x < nw) ? sh[threadIdx.x]      : 0.f;
        ss = (threadIdx.x < nw) ? sh[32 + threadIdx.x] : 0.f;
        for (int o = 16; o; o >>= 1) {
            s  += __shfl_down_sync(0xffffffffu, s, o);
            ss += __shfl_down_sync(0xffffffffu, ss, o);
        }
        if (threadIdx.x == 0) {
            part[((size_t)n * gridDim.x + blockIdx.x) * 2 + 0] = s;
            part[((size_t)n * gridDim.x + blockIdx.x) * 2 + 1] = ss;
        }
    }
}

__global__ void reduce2_kernel(const float* __restrict__ part, int nb, float* __restrict__ stats) {
    int n = blockIdx.x;
    float s = 0.f, ss = 0.f;
    for (int i = threadIdx.x; i < nb; i += blockDim.x) {
        s  += part[((size_t)n * nb + i) * 2 + 0];
        ss += part[((size_t)n * nb + i) * 2 + 1];
    }
    for (int o = 16; o; o >>= 1) {
        s  += __shfl_down_sync(0xffffffffu, s, o);
        ss += __shfl_down_sync(0xffffffffu, ss, o);
    }
    __shared__ float sh[64];
    int w = threadIdx.x >> 5;
    if ((threadIdx.x & 31) == 0) { sh[w] = s; sh[32 + w] = ss; }
    __syncthreads();
    if (threadIdx.x < 32) {
        int nw = blockDim.x >> 5;
        s  = (threadIdx.x < nw) ? sh[threadIdx.x]      : 0.f;
        ss = (threadIdx.x < nw) ? sh[32 + threadIdx.x] : 0.f;
        for (int o = 16; o; o >>= 1) {
            s  += __shfl_down_sync(0xffffffffu, s, o);
            ss += __shfl_down_sync(0xffffffffu, ss, o);
        }
        if (threadIdx.x == 0) { stats[n * 2] = s; stats[n * 2 + 1] = ss; }
    }
}

__global__ void make_affine_kernel(const float* __restrict__ stats,
                                   const float* __restrict__ w, const float* __restrict__ b,
                                   float* __restrict__ a, float* __restrict__ d, float inv_cnt) {
    int c = threadIdx.x;
    int n = blockIdx.x;
    float mean = stats[n * 2] * inv_cnt;
    float var  = stats[n * 2 + 1] * inv_cnt - mean * mean;
    float rstd = rsqrtf(var + EPS);
    a[n * CH + c] = w[c] * rstd;
    d[n * CH + c] = b[c] - mean * rstd * w[c];
}

__global__ void convert_x_kernel(const float* __restrict__ x,
                                 const float* __restrict__ a, const float* __restrict__ d,
                                 __nv_bfloat16* __restrict__ out) {
    size_t i4 = (size_t)blockIdx.x * blockDim.x + threadIdx.x;
    int c = (int)((i4 >> 13) & 255);
    int n = (int)(i4 >> 21);
    float aa = a[n * CH + c], dd = d[n * CH + c];
    float4 v = reinterpret_cast<const float4*>(x)[i4];
    uint2 r;
    r.x = pack2(fmaf(aa, v.x, dd), fmaf(aa, v.y, dd));
    r.y = pack2(fmaf(aa, v.z, dd), fmaf(aa, v.w, dd));
    reinterpret_cast<uint2*>(out)[i4] = r;
}

__global__ void apply_pool_affine_kernel(const float* __restrict__ praw,
                                         const float* __restrict__ a, const float* __restrict__ d,
                                         float* __restrict__ pnorm) {
    size_t i4 = (size_t)blockIdx.x * blockDim.x + threadIdx.x;
    int c = (int)((i4 >> 7) & 255);
    int n = (int)(i4 >> 15);
    float aa = a[n * CH + c], dd = d[n * CH + c];
    float4 v = reinterpret_cast<const float4*>(praw)[i4];
    v.x = fmaf(aa, v.x, dd); v.y = fmaf(aa, v.y, dd);
    v.z = fmaf(aa, v.z, dd); v.w = fmaf(aa, v.w, dd);
    reinterpret_cast<float4*>(pnorm)[i4] = v;
}

__global__ void convert_pooled_kernel(const float* __restrict__ pooled,
                                      const float* __restrict__ a, const float* __restrict__ d,
                                      __nv_bfloat16* __restrict__ out) {
    size_t i4 = (size_t)blockIdx.x * blockDim.x + threadIdx.x;
    int c = (int)((i4 >> 7) & 255);
    int n = (int)(i4 >> 15);
    float aa = a[n * CH + c], dd = d[n * CH + c];
    float4 v = reinterpret_cast<const float4*>(pooled)[i4];
    uint2 r;
    r.x = pack2(fmaf(aa, v.x, dd), fmaf(aa, v.y, dd));
    r.y = pack2(fmaf(aa, v.z, dd), fmaf(aa, v.w, dd));
    reinterpret_cast<uint2*>(out)[i4] = r;
}

__global__ void convert_weights_kernel(
    const float* __restrict__ qkv_w, const float* __restrict__ q_w,
    const float* __restrict__ kv_w, const float* __restrict__ proj_w,
    __nv_bfloat16* __restrict__ Wqkv, __nv_bfloat16* __restrict__ Wq,
    __nv_bfloat16* __restrict__ Wkv, __nv_bfloat16* __restrict__ Wproj) {
    int idx = blockIdx.x * blockDim.x + threadIdx.x;
    const int T1 = 768 * 256, T2 = T1 + 256 * 256, T3 = T2 + 512 * 256, T4 = T3 + 256 * 768;
    if (idx < T1) {
        Wqkv[idx] = __float2bfloat16(qkv_w[idx]);
    } else if (idx < T2) {
        int j = idx - T1; Wq[j] = __float2bfloat16(q_w[j]);
    } else if (idx < T3) {
        int j = idx - T2; Wkv[j] = __float2bfloat16(kv_w[j]);
    } else if (idx < T4) {
        int j = idx - T3;
        int m = j / 768, k = j % 768;
        float v = proj_w[m * 256 + (k & 255)];
        __nv_bfloat16 hi = __float2bfloat16(v);
        if (k >= 256 && k < 512) hi = __float2bfloat16(v - __bfloat162float(hi));
        Wproj[j] = hi;
    }
}

// =========================================================================
// wgemm3: BM=128, BN=128, BK=32, 3-stage cp.async, 256 threads.
// =========================================================================
#define WG_SMEM 69632

template<int MODE>
__global__ void __launch_bounds__(256) wgemm3_kernel(
    const __nv_bfloat16* __restrict__ A,
    const __nv_bfloat16* __restrict__ B0, const __nv_bfloat16* __restrict__ B1,
    const float* __restrict__ bias,
    float* __restrict__ outF, __nv_bfloat16* __restrict__ outB,
    int M, int S, int KT, float qScale) {
    extern __shared__ __align__(16) char dsm[];
    __nv_bfloat16* As = (__nv_bfloat16*)dsm;
    __nv_bfloat16* Bs = (__nv_bfloat16*)(dsm + 30720);
    float* Cs = (float*)dsm;

    int tid = threadIdx.x, warp = tid >> 5;
    int wm = warp >> 2, wn = warp & 3;
    int m0 = blockIdx.x * 128;
    int s0 = blockIdx.y * 128;
    int z  = blockIdx.z;

    const __nv_bfloat16* Bb0 = B0 + (size_t)z * 256 * S;
    const __nv_bfloat16* Bb1 = B1 + (size_t)z * 256 * S;

    wmma::fragment<wmma::accumulator, 16, 16, 16, float> acc[4][2];
    #pragma unroll
    for (int i = 0; i < 4; i++)
        #pragma unroll
        for (int j = 0; j < 2; j++) wmma::fill_fragment(acc[i][j], 0.f);

    const int NIT = KT >> 5;

    auto prefetch = [&](int it, int buf) {
        int ktL = it * 32;
        #pragma unroll
        for (int i = 0; i < 2; i++) {
            int c = tid + i * 256;
            int r = c >> 2, q = (c & 3) * 8;
            cp16(As + buf * 5120 + r * 40 + q,
                 A + (size_t)(m0 + r) * KT + ktL + q);
        }
        const __nv_bfloat16* Bp = (ktL < 512) ? Bb0 : Bb1;
        int krow = ktL & 255;
        #pragma unroll
        for (int i = 0; i < 2; i++) {
            int c = tid + i * 256;
            int r = c >> 4, q = (c & 15) * 8;
            cp16(Bs + buf * 4352 + r * 136 + q,
                 Bp + (size_t)(krow + r) * S + s0 + q);
        }
    };

    prefetch(0, 0); CP_COMMIT;
    prefetch(1, 1); CP_COMMIT;

    int buf = 0;
    for (int it = 0; it < NIT; it++) {
        if (it + 1 < NIT) CP_WAIT1; else CP_WAIT0;
        __syncthreads();
        #pragma unroll
        for (int ks = 0; ks < 2; ks++) {
            wmma::fragment<wmma::matrix_a, 16, 16, 16, __nv_bfloat16, wmma::row_major> af[4];
            #pragma unroll
            for (int i = 0; i < 4; i++)
                wmma::load_matrix_sync(af[i], As + buf * 5120 + (wm * 64 + i * 16) * 40 + ks * 16, 40);
            wmma::fragment<wmma::matrix_b, 16, 16, 16, __nv_bfloat16, wmma::row_major> bf[2];
            #pragma unroll
            for (int j = 0; j < 2; j++)
                wmma::load_matrix_sync(bf[j], Bs + buf * 4352 + (ks * 16) * 136 + wn * 32 + j * 16, 136);
            #pragma unroll
            for (int i = 0; i < 4; i++)
                #pragma unroll
                for (int j = 0; j < 2; j++)
                    wmma::mma_sync(acc[i][j], af[i], bf[j], acc[i][j]);
        }
        if (it + 2 < NIT) {
            prefetch(it + 2, (buf + 2) % 3);
            CP_COMMIT;
        }
        buf = (buf + 1) % 3;
    }

    __syncthreads();
    #pragma unroll
    for (int i = 0; i < 4; i++)
        #pragma unroll
        for (int j = 0; j < 2; j++)
            wmma::store_matrix_sync(Cs + (wm * 64 + i * 16) * 132 + wn * 32 + j * 16,
                                    acc[i][j], 132, wmma::mem_row_major);
    __syncthreads();

    if (MODE == 0) {
        float* Ob = outF + ((size_t)z * M + m0) * S;
        #pragma unroll
        for (int it = 0; it < 16; it++) {
            int idx = tid + it * 256;
            int r = idx >> 5, c4 = idx & 31;
            float bv = bias[m0 + r];
            float4 v = *reinterpret_cast<const float4*>(&Cs[r * 132 + c4 * 4]);
            v.x += bv; v.y += bv; v.z += bv; v.w += bv;
            *reinterpret_cast<float4*>(&Ob[(size_t)r * S + s0 + c4 * 4]) = v;
        }
    } else {
        #pragma unroll
        for (int it = 0; it < 8; it++) {
            int idx = tid + it * 256;
            int sl = idx & 127, dg = idx >> 7;
            int gmb = m0 + dg * 8;
            float sc;
            size_t off;
            __nv_bfloat16* base;
            if (MODE == 1) {
                int hb = gmb >> 6, db = gmb & 63;
                sc = qScale;
                base = outB + ((size_t)(z * (M >> 6) + hb) * S + s0 + sl) * 64;
                off = db;
            } else {
                int sel = gmb >> 8, head = (gmb >> 6) & 3, db = gmb & 63;
                sc = (sel == 0) ? qScale : 1.f;
                int s = s0 + sl;
                int d5 = s & 31, w5 = (s >> 5) & 31, h5 = s >> 10;
                int window = ((h5 >> 2) * 8 + (w5 >> 2)) * 8 + (d5 >> 2);
                int token  = (((h5 & 3) * 4 + (w5 & 3)) * 4 + (d5 & 3));
                base = outB + (((size_t)(z * 3 + sel) * 4 + head) * 512) * 4096;
                off = (size_t)window * 4096 + token * 64 + db;
            }
            float f[8];
            #pragma unroll
            for (int e = 0; e < 8; e++)
                f[e] = (Cs[(dg * 8 + e) * 132 + sl] + bias[gmb + e]) * sc;
            uint4 u;
            u.x = pack2(f[0], f[1]);
            u.y = pack2(f[2], f[3]);
            u.z = pack2(f[4], f[5]);
            u.w = pack2(f[6], f[7]);
            *reinterpret_cast<uint4*>(base + off) = u;
        }
    }
}

// =========================================================================
// Local windowed attention (wmma, no-max softmax) + pool sums + gn partials
// =========================================================================
__global__ void __launch_bounds__(128) local_attn_w_kernel(
    const __nv_bfloat16* __restrict__ qkvB, const float* __restrict__ x,
    float* __restrict__ attn, float* __restrict__ praw, float* __restrict__ part) {
    __shared__ __align__(16) __nv_bfloat16 QP[64 * 72];
    __shared__ __align__(16) __nv_bfloat16 Ks[64 * 72];
    __shared__ __align__(16) __nv_bfloat16 Vs[64 * 72];
    __shared__ __align__(16) float Sf[64 * 68];
    __shared__ float linv[64];
    __shared__ float rs[4], rss[4];

    int w = blockIdx.x, head = blockIdx.y, n = blockIdx.z;
    int tid = threadIdx.x, warp = tid >> 5;

    size_t base = (((size_t)(n * 3) * 4 + head) * 512 + w) * 4096;
    size_t step = (size_t)4 * 512 * 4096;
    const uint4* Qg = (const uint4*)(qkvB + base);
    const uint4* Kg = (const uint4*)(qkvB + base + step);
    const uint4* Vg = (const uint4*)(qkvB + base + 2 * step);

    #pragma unroll
    for (int i = 0; i < 4; i++) {
        int c = tid + i * 128;
        int r = c >> 3, q = c & 7;
        ((uint4*)(QP + r * 72))[q] = Qg[c];
        ((uint4*)(Ks + r * 72))[q] = Kg[c];
        ((uint4*)(Vs + r * 72))[q] = Vg[c];
    }
    __syncthreads();

    {
        int m = warp * 16;
        wmma::fragment<wmma::accumulator, 16, 16, 16, float> acc[4];
        #pragma unroll
        for (int j = 0; j < 4; j++) wmma::fill_fragment(acc[j], 0.f);
        #pragma unroll
        for (int kd = 0; kd < 4; kd++) {
            wmma::fragment<wmma::matrix_a, 16, 16, 16, __nv_bfloat16, wmma::row_major> af;
            wmma::load_matrix_sync(af, QP + m * 72 + kd * 16, 72);
            #pragma unroll
            for (int j = 0; j < 4; j++) {
                wmma::fragment<wmma::matrix_b, 16, 16, 16, __nv_bfloat16, wmma::col_major> bf;
                wmma::load_matrix_sync(bf, Ks + (j * 16) * 72 + kd * 16, 72);
                wmma::mma_sync(acc[j], af, bf, acc[j]);
            }
        }
        #pragma unroll
        for (int j = 0; j < 4; j++)
            wmma::store_matrix_sync(Sf + m * 68 + j * 16, acc[j], 68, wmma::mem_row_major);
    }
    __syncthreads();

    // softmax without max subtraction (scores are tiny; softmax is shift-invariant)
    {
        int r = tid >> 1, hf = tid & 1;
        const float* srow = Sf + r * 68 + hf * 32;
        float ls = 0.f;
        __nv_bfloat16* prow = QP + r * 72 + hf * 32;
        #pragma unroll
        for (int j = 0; j < 32; j++) {
            float p = __expf(srow[j]);
            ls += p;
            prow[j] = __float2bfloat16(p);
        }
        ls += __shfl_xor_sync(0xffffffffu, ls, 1);
        if (hf == 0) linv[r] = 1.f / ls;
    }
    __syncthreads();

    {
        int m = warp * 16;
        wmma::fragment<wmma::accumulator, 16, 16, 16, float> acc[4];
        #pragma unroll
        for (int j = 0; j < 4; j++) wmma::fill_fragment(acc[j], 0.f);
        #pragma unroll
        for (int kk = 0; kk < 4; kk++) {
            wmma::fragment<wmma::matrix_a, 16, 16, 16, __nv_bfloat16, wmma::row_major> af;
            wmma::load_matrix_sync(af, QP + m * 72 + kk * 16, 72);
            #pragma unroll
            for (int j = 0; j < 4; j++) {
                wmma::fragment<wmma::matrix_b, 16, 16, 16, __nv_bfloat16, wmma::row_major> bf;
                wmma::load_matrix_sync(bf, Vs + (kk * 16) * 72 + j * 16, 72);
                wmma::mma_sync(acc[j], af, bf, acc[j]);
            }
        }
        #pragma unroll
        for (int j = 0; j < 4; j++)
            wmma::store_matrix_sync(Sf + m * 68 + j * 16, acc[j], 68, wmma::mem_row_major);
    }
    __syncthreads();

    int wh = w >> 6, ww = (w >> 3) & 7, wd = w & 7;
    int base_s = wh * 4096 + ww * 128 + wd * 4;
    int chb = n * 256 + head * 64;
    float s_acc = 0.f, ss_acc = 0.f;
    #pragma unroll
    for (int it = 0; it < 8; it++) {
        int idx = tid + it * 128;
        int d = idx >> 4, tg = idx & 15;
        int i_ = tg >> 2, j_ = tg & 3;
        int s = base_s + i_ * 1024 + j_ * 32;
        int t0 = tg * 4;
        size_t g = ((size_t)(chb + d)) * SV + s;
        float4 xv = *reinterpret_cast<const float4*>(x + g);
        float4 ov;
        ov.x = fmaf(Sf[(t0 + 0) * 68 + d], linv[t0 + 0], xv.x);
        ov.y = fmaf(Sf[(t0 + 1) * 68 + d], linv[t0 + 1], xv.y);
        ov.z = fmaf(Sf[(t0 + 2) * 68 + d], linv[t0 + 2], xv.z);
        ov.w = fmaf(Sf[(t0 + 3) * 68 + d], linv[t0 + 3], xv.w);
        *reinterpret_cast<float4*>(attn + g) = ov;
        float ps = ov.x + ov.y + ov.z + ov.w;
        s_acc  += ps;
        ss_acc += ov.x*ov.x + ov.y*ov.y + ov.z*ov.z + ov.w*ov.w;
        #pragma unroll
        for (int o = 8; o; o >>= 1) ps += __shfl_down_sync(0xffffffffu, ps, o);
        if ((tid & 15) == 0)
            praw[((size_t)(chb + d)) * 512 + w] = ps * (1.f / 64.f);
    }
    #pragma unroll
    for (int o = 16; o; o >>= 1) {
        s_acc  += __shfl_down_sync(0xffffffffu, s_acc, o);
        ss_acc += __shfl_down_sync(0xffffffffu, ss_acc, o);
    }
    if ((tid & 31) == 0) { rs[warp] = s_acc; rss[warp] = ss_acc; }
    __syncthreads();
    if (tid == 0) {
        size_t pi = (size_t)n * 2048 + head * 512 + w;
        part[pi * 2 + 0] = rs[0] + rs[1] + rs[2] + rs[3];
        part[pi * 2 + 1] = rss[0] + rss[1] + rss[2] + rss[3];
    }
}

// =========================================================================
// Global attention v2: no-max softmax, O persistent in wmma accumulators,
// 64-key chunks, 90.6 KB smem -> 2 blocks/SM.
// =========================================================================
#define GA_SMEM 90624

__global__ void __launch_bounds__(256, 2) gattn_kernel(
    const __nv_bfloat16* __restrict__ q2T, const __nv_bfloat16* __restrict__ kvT,
    const float* __restrict__ attn,
    const float* __restrict__ A1, const float* __restrict__ D1,
    __nv_bfloat16* __restrict__ ghi, __nv_bfloat16* __restrict__ glo) {
    extern __shared__ __align__(16) char sm[];
    __nv_bfloat16* Qs = (__nv_bfloat16*)sm;          // [128][72]
    __nv_bfloat16* Ks = Qs + 128 * 72;               // [64][72]
    __nv_bfloat16* Vs = Ks + 64 * 72;                // [64][72]
    __nv_bfloat16* Ps = Vs + 64 * 72;                // [128][72]
    float* Sf   = (float*)(Ps + 128 * 72);           // [128][68]
    float* lrow = Sf + 128 * 68;                     // [128]

    int tid = threadIdx.x, warp = tid >> 5;
    int h = blockIdx.y, n = blockIdx.z;
    int s0 = blockIdx.x * 128;

    const uint4* Qg = (const uint4*)(q2T + ((size_t)(n * 4 + h) * SV + s0) * 64);
    const uint4* Kg = (const uint4*)(kvT + ((size_t)(n * 8 + h) * 512) * 64);
    const uint4* Vg = (const uint4*)(kvT + ((size_t)(n * 8 + 4 + h) * 512) * 64);

    #pragma unroll
    for (int i = 0; i < 4; i++) {
        int idx = tid + i * 256;
        int r = idx >> 3, c = idx & 7;
        ((uint4*)(Qs + r * 72))[c] = Qg[r * 8 + c];
    }
    if (tid < 128) lrow[tid] = 0.f;

    // persistent O accumulators: warp grid 4(M) x 2(N), tile 32x32
    int pm = warp >> 1, pn = warp & 1;
    wmma::fragment<wmma::accumulator, 16, 16, 16, float> acc_o[2][2];
    #pragma unroll
    for (int i = 0; i < 2; i++)
        #pragma unroll
        for (int j = 0; j < 2; j++) wmma::fill_fragment(acc_o[i][j], 0.f);

    for (int ch = 0; ch < 8; ch++) {
        __syncthreads();   // prev PV done; lrow/Q ready on first iter
        #pragma unroll
        for (int i = 0; i < 2; i++) {
            int idx = tid + i * 256;
            int r = idx >> 3, c = idx & 7;
            ((uint4*)(Ks + r * 72))[c] = Kg[(ch * 64 + r) * 8 + c];
            ((uint4*)(Vs + r * 72))[c] = Vg[(ch * 64 + r) * 8 + c];
        }
        __syncthreads();

        // S = Q @ K^T : each warp 16 rows x 64 keys
        {
            int m = warp * 16;
            wmma::fragment<wmma::accumulator, 16, 16, 16, float> acc[4];
            #pragma unroll
            for (int j = 0; j < 4; j++) wmma::fill_fragment(acc[j], 0.f);
            #pragma unroll
            for (int kd = 0; kd < 4; kd++) {
                wmma::fragment<wmma::matrix_a, 16, 16, 16, __nv_bfloat16, wmma::row_major> af;
                wmma::load_matrix_sync(af, Qs + m * 72 + kd * 16, 72);
                #pragma unroll
                for (int j = 0; j < 4; j++) {
                    wmma::fragment<wmma::matrix_b, 16, 16, 16, __nv_bfloat16, wmma::col_major> bf;
                    wmma::load_matrix_sync(bf, Ks + (j * 16) * 72 + kd * 16, 72);
                    wmma::mma_sync(acc[j], af, bf, acc[j]);
                }
            }
            #pragma unroll
            for (int j = 0; j < 4; j++)
                wmma::store_matrix_sync(Sf + m * 68 + j * 16, acc[j], 68, wmma::mem_row_major);
        }
        __syncthreads();

        // softmax-lite: p = exp(s), accumulate row sums
        {
            int r = tid >> 1, hf = tid & 1;
            const float* srow = Sf + r * 68 + hf * 32;
            float ls = 0.f;
            __nv_bfloat16* prow = Ps + r * 72 + hf * 32;
            #pragma unroll
            for (int j = 0; j < 32; j++) {
                float p = __expf(srow[j]);
                ls += p;
                prow[j] = __float2bfloat16(p);
            }
            ls += __shfl_xor_sync(0xffffffffu, ls, 1);
            if (hf == 0) lrow[r] += ls;
        }
        __syncthreads();

        // O += P @ V (persistent accumulators)
        {
            #pragma unroll
            for (int kk = 0; kk < 4; kk++) {
                wmma::fragment<wmma::matrix_a, 16, 16, 16, __nv_bfloat16, wmma::row_major> af[2];
                #pragma unroll
                for (int i = 0; i < 2; i++)
                    wmma::load_matrix_sync(af[i], Ps + (pm * 32 + i * 16) * 72 + kk * 16, 72);
                wmma::fragment<wmma::matrix_b, 16, 16, 16, __nv_bfloat16, wmma::row_major> bf[2];
                #pragma unroll
                for (int j = 0; j < 2; j++)
                    wmma::load_matrix_sync(bf[j], Vs + (kk * 16) * 72 + pn * 32 + j * 16, 72);
                #pragma unroll
                for (int i = 0; i < 2; i++)
                    #pragma unroll
                    for (int j = 0; j < 2; j++)
                        wmma::mma_sync(acc_o[i][j], af[i], bf[j], acc_o[i][j]);
            }
        }
    }

    // stage O to smem once, then coalesced epilogue
    __syncthreads();
    #pragma unroll
    for (int i = 0; i < 2; i++)
        #pragma unroll
        for (int j = 0; j < 2; j++)
            wmma::store_matrix_sync(Sf + (pm * 32 + i * 16) * 68 + pn * 32 + j * 16,
                                    acc_o[i][j], 68, wmma::mem_row_major);
    __syncthreads();

    #pragma unroll
    for (int i = 0; i < 32; i++) {
        int idx = tid + i * 256;
        int r = idx & 127, d = idx >> 7;
        int cch = n * 256 + h * 64 + d;
        float v = Sf[r * 68 + d] / lrow[r];
        size_t gi = ((size_t)cch) * SV + s0 + r;
        float t = v + fmaf(A1[cch], attn[gi], D1[cch]);
        __nv_bfloat16 hi = __float2bfloat16(t);
        ghi[gi] = hi;
        glo[gi] = __float2bfloat16(t - __bfloat162float(hi));
    }
}

// =========================================================================
// host launch
// =========================================================================
extern "C" void kernel_launch(void* const* d_in, const int* in_sizes, int n_in,
                              void* d_out, int out_size) {
    const float* x      = (const float*)d_in[0];
    const float* qkv_w  = (const float*)d_in[1];
    const float* qkv_b  = (const float*)d_in[2];
    const float* norm_w = (const float*)d_in[3];
    const float* norm_b = (const float*)d_in[4];
    const float* anorm_w= (const float*)d_in[5];
    const float* anorm_b= (const float*)d_in[6];
    const float* dnorm_w= (const float*)d_in[7];
    const float* dnorm_b= (const float*)d_in[8];
    const float* q_w    = (const float*)d_in[9];
    const float* q_b    = (const float*)d_in[10];
    const float* kv_w   = (const float*)d_in[11];
    const float* kv_b   = (const float*)d_in[12];
    const float* proj_w = (const float*)d_in[13];
    const float* proj_b = (const float*)d_in[14];
    float* out = (float*)d_out;

    float *attn, *praw, *pnorm, *part, *stats, *aff;
    __nv_bfloat16 *xnB, *qkvB, *attnB, *ghi, *glo, *pooledB, *q2T, *kvT;
    __nv_bfloat16 *WqkvB, *WqB, *WkvB, *WprojB;
    cudaGetSymbolAddress((void**)&attn,    g_attn);
    cudaGetSymbolAddress((void**)&praw,    g_praw);
    cudaGetSymbolAddress((void**)&pnorm,   g_pnorm);
    cudaGetSymbolAddress((void**)&xnB,     g_xnB);
    cudaGetSymbolAddress((void**)&qkvB,    g_qkvB);
    cudaGetSymbolAddress((void**)&attnB,   g_attnB);
    cudaGetSymbolAddress((void**)&ghi,     g_ghi);
    cudaGetSymbolAddress((void**)&glo,     g_glo);
    cudaGetSymbolAddress((void**)&pooledB, g_pooledB);
    cudaGetSymbolAddress((void**)&q2T,     g_q2T);
    cudaGetSymbolAddress((void**)&kvT,     g_kvT);
    cudaGetSymbolAddress((void**)&WqkvB,   g_WqkvB);
    cudaGetSymbolAddress((void**)&WqB,     g_WqB);
    cudaGetSymbolAddress((void**)&WkvB,    g_WkvB);
    cudaGetSymbolAddress((void**)&WprojB,  g_WprojB);
    cudaGetSymbolAddress((void**)&part,    g_part);
    cudaGetSymbolAddress((void**)&stats,   g_stats);
    cudaGetSymbolAddress((void**)&aff,     g_aff);

    static bool attr_set = false;
    if (!attr_set) {
        cudaFuncSetAttribute(gattn_kernel, cudaFuncAttributeMaxDynamicSharedMemorySize, GA_SMEM);
        cudaFuncSetAttribute(wgemm3_kernel<0>, cudaFuncAttributeMaxDynamicSharedMemorySize, WG_SMEM);
        cudaFuncSetAttribute(wgemm3_kernel<1>, cudaFuncAttributeMaxDynamicSharedMemorySize, WG_SMEM);
        cudaFuncSetAttribute(wgemm3_kernel<2>, cudaFuncAttributeMaxDynamicSharedMemorySize, WG_SMEM);
        attr_set = true;
    }

    float* A0 = aff;        float* D0 = aff + 512;
    float* A1 = aff + 1024; float* D1 = aff + 1536;
    float* A2 = aff + 2048; float* D2 = aff + 2560;

    convert_weights_kernel<<<2304, 256>>>(qkv_w, q_w, kv_w, proj_w,
                                          WqkvB, WqB, WkvB, WprojB);

    reduce1_kernel<<<dim3(512, NB), 256>>>(x, 256L * SV, part);
    reduce2_kernel<<<NB, 256>>>(part, 512, stats);
    make_affine_kernel<<<NB, 256>>>(stats, norm_w, norm_b, A0, D0, 1.f / (256.f * 32768.f));
    convert_x_kernel<<<16384, 256>>>(x, A0, D0, xnB);

    wgemm3_kernel<2><<<dim3(6, 256, NB), 256, WG_SMEM>>>(
        WqkvB, xnB, xnB, qkv_b, nullptr, qkvB, 768, (int)SV, 256, SCALE_INV);

    local_attn_w_kernel<<<dim3(512, NH, NB), 128>>>(qkvB, x, attn, praw, part);

    reduce2_kernel<<<NB, 256>>>(part, 2048, stats);
    make_affine_kernel<<<NB, 256>>>(stats, anorm_w, anorm_b, A1, D1, 1.f / (256.f * 32768.f));

    convert_x_kernel<<<16384, 256>>>(attn, A1, D1, attnB);

    apply_pool_affine_kernel<<<256, 256>>>(praw, A1, D1, pnorm);
    reduce1_kernel<<<dim3(32, NB), 256>>>(pnorm, 256L * 512, part);
    reduce2_kernel<<<NB, 256>>>(part, 32, stats);
    make_affine_kernel<<<NB, 256>>>(stats, dnorm_w, dnorm_b, A2, D2, 1.f / (256.f * 512.f));
    convert_pooled_kernel<<<256, 256>>>(pnorm, A2, D2, pooledB);

    wgemm3_kernel<1><<<dim3(4, 4, NB), 256, WG_SMEM>>>(
        WkvB, pooledB, pooledB, kv_b, nullptr, kvT, 512, 512, 256, 1.f);
    wgemm3_kernel<1><<<dim3(2, 256, NB), 256, WG_SMEM>>>(
        WqB, attnB, attnB, q_b, nullptr, q2T, 256, (int)SV, 256, SCALE_INV);

    gattn_kernel<<<dim3(256, NH, NB), 256, GA_SMEM>>>(q2T, kvT, attn, A1, D1, ghi, glo);

    wgemm3_kernel<0><<<dim3(2, 256, NB), 256, WG_SMEM>>>(
        WprojB, ghi, glo, proj_b, out, nullptr, 256, (int)SV, 768, 1.f);
}